// round 1
// baseline (speedup 1.0000x reference)
#include <cuda_runtime.h>
#include <cuda_bf16.h>
#include <math.h>

// Problem constants
#define Bx 4
#define Tseq 2048
#define Dm 1024
#define NH 8
#define HD 128
#define KD 128           // NKV * HD
#define SOFTCAP 30.0f

// Scratch (device globals; no allocation allowed)
__device__ float g_Q[(size_t)Bx * Tseq * Dm];   // 32MB, roped+gained Q
__device__ float g_K[(size_t)Bx * Tseq * KD];   // 4MB, roped K
__device__ float g_V[(size_t)Bx * Tseq * KD];   // 4MB
__device__ float g_AO[(size_t)Bx * Tseq * Dm];  // 32MB attention output

// ---------------------------------------------------------------------------
// GEMM: C[M,N] = A[M,K] @ W[N,K]^T   (fp32, 128x128x16 tiles, 256 threads)
// ---------------------------------------------------------------------------
__global__ __launch_bounds__(256) void gemm_nt_kernel(
    const float* __restrict__ A, const float* __restrict__ W,
    float* __restrict__ C, int M, int N, int K)
{
    const int BM = 128, BN = 128, BK = 16;
    __shared__ __align__(16) float As[BK][BM];
    __shared__ __align__(16) float Ws[BK][BN];

    int m0 = blockIdx.y * BM;
    int n0 = blockIdx.x * BN;
    int tid = threadIdx.x;
    int ty = tid >> 4;      // 0..15  -> rows ty*8..ty*8+7
    int tx = tid & 15;      // 0..15  -> cols tx*8..tx*8+7

    float acc[8][8];
#pragma unroll
    for (int i = 0; i < 8; i++)
#pragma unroll
        for (int j = 0; j < 8; j++) acc[i][j] = 0.f;

    for (int k0 = 0; k0 < K; k0 += BK) {
        // Load 128x16 tiles of A and W (transposed into smem)
#pragma unroll
        for (int i = 0; i < 2; i++) {
            int j = tid + i * 256;        // 0..511 float4 units
            int row = j >> 2;
            int ks = (j & 3) * 4;
            float4 va = *(const float4*)&A[(size_t)(m0 + row) * K + k0 + ks];
            As[ks + 0][row] = va.x; As[ks + 1][row] = va.y;
            As[ks + 2][row] = va.z; As[ks + 3][row] = va.w;
            float4 vw = *(const float4*)&W[(size_t)(n0 + row) * K + k0 + ks];
            Ws[ks + 0][row] = vw.x; Ws[ks + 1][row] = vw.y;
            Ws[ks + 2][row] = vw.z; Ws[ks + 3][row] = vw.w;
        }
        __syncthreads();

#pragma unroll
        for (int kk = 0; kk < BK; kk++) {
            float a[8], b[8];
            *(float4*)&a[0] = *(const float4*)&As[kk][ty * 8];
            *(float4*)&a[4] = *(const float4*)&As[kk][ty * 8 + 4];
            *(float4*)&b[0] = *(const float4*)&Ws[kk][tx * 8];
            *(float4*)&b[4] = *(const float4*)&Ws[kk][tx * 8 + 4];
#pragma unroll
            for (int i = 0; i < 8; i++)
#pragma unroll
                for (int j = 0; j < 8; j++)
                    acc[i][j] += a[i] * b[j];
        }
        __syncthreads();
    }

#pragma unroll
    for (int i = 0; i < 8; i++) {
        float* crow = &C[(size_t)(m0 + ty * 8 + i) * N + n0 + tx * 8];
        *(float4*)&crow[0] = make_float4(acc[i][0], acc[i][1], acc[i][2], acc[i][3]);
        *(float4*)&crow[4] = make_float4(acc[i][4], acc[i][5], acc[i][6], acc[i][7]);
    }
}

// ---------------------------------------------------------------------------
// RoPE (in place). Q layout [B*T, NH*HD]; K layout [B*T, HD].
// ---------------------------------------------------------------------------
__global__ void rope_q_kernel(float* __restrict__ Q,
                              const float* __restrict__ cosb,
                              const float* __restrict__ sinb,
                              const float* __restrict__ gain)
{
    int idx = blockIdx.x * blockDim.x + threadIdx.x;   // B*T*NH*64
    if (idx >= Bx * Tseq * NH * 64) return;
    int d = idx & 63;
    int h = (idx >> 6) & (NH - 1);
    int bt = idx >> 9;                // / (NH*64)
    int t = bt & (Tseq - 1);
    size_t base = (size_t)bt * Dm + h * HD + d;
    float x1 = Q[base], x2 = Q[base + 64];
    float c = cosb[t * 64 + d], s = sinb[t * 64 + d];
    float g = gain[h];
    Q[base]      = (x1 * c - x2 * s) * g;
    Q[base + 64] = (x1 * s + x2 * c) * g;
}

__global__ void rope_k_kernel(float* __restrict__ K,
                              const float* __restrict__ cosb,
                              const float* __restrict__ sinb)
{
    int idx = blockIdx.x * blockDim.x + threadIdx.x;   // B*T*64
    if (idx >= Bx * Tseq * 64) return;
    int d = idx & 63;
    int bt = idx >> 6;
    int t = bt & (Tseq - 1);
    size_t base = (size_t)bt * KD + d;
    float x1 = K[base], x2 = K[base + 64];
    float c = cosb[t * 64 + d], s = sinb[t * 64 + d];
    K[base]      = x1 * c - x2 * s;
    K[base + 64] = x1 * s + x2 * c;
}

// ---------------------------------------------------------------------------
// Flash-style causal attention with softcap. MQA (1 KV head).
// Block: (q-tile of 64, head, batch). 256 threads.
// Softcapped scores are bounded by 30, so exp() never overflows fp32 and we
// can skip online-max rescaling entirely: acc += exp(s)*V, l += exp(s).
// smem tiles: Qst [HD][BQ] k-major, Kst [HD][BKT] k-major, Vs [BKT][HD],
// Pst [BKT][BQ] (k-major for the PV phase).
// ---------------------------------------------------------------------------
#define BQ 64
#define BKT 128
#define SQ 65      // Qst row stride
#define SK 129     // Kst row stride
#define SV 128     // Vs row stride
#define SP 65      // Pst row stride
#define ATTN_SMEM_FLOATS (HD*SQ + HD*SK + BKT*SV + BKT*SP + BQ)

__global__ __launch_bounds__(256) void attn_kernel(
    const float* __restrict__ Q, const float* __restrict__ Kg,
    const float* __restrict__ Vg, float* __restrict__ AO)
{
    extern __shared__ float sm[];
    float* Qst = sm;                    // [128][SQ]
    float* Kst = Qst + HD * SQ;         // [128][SK]
    float* Vs  = Kst + HD * SK;         // [BKT][SV]
    float* Pst = Vs + BKT * SV;         // [BKT][SP]
    float* Ls  = Pst + BKT * SP;        // [BQ]

    int q0 = blockIdx.x * BQ;
    int h  = blockIdx.y;
    int b  = blockIdx.z;
    int tid = threadIdx.x;
    int rg = tid >> 4;     // rows 4*rg .. 4*rg+3
    int cg = tid & 15;     // cols cg + 16*j, j=0..7

    // --- load Q tile (transposed to k-major) ---
    const size_t qbase = ((size_t)b * Tseq + q0) * Dm + h * HD;
#pragma unroll
    for (int i = 0; i < 8; i++) {
        int j = tid + i * 256;      // 0..2047 float4 units; 32 per row
        int r = j >> 5;
        int s = j & 31;
        float4 v = *(const float4*)&Q[qbase + (size_t)r * Dm + s * 4];
        int d = s * 4;
        Qst[(d + 0) * SQ + r] = v.x; Qst[(d + 1) * SQ + r] = v.y;
        Qst[(d + 2) * SQ + r] = v.z; Qst[(d + 3) * SQ + r] = v.w;
    }
    if (tid < BQ) Ls[tid] = 0.f;

    float acc[4][8];
#pragma unroll
    for (int i = 0; i < 4; i++)
#pragma unroll
        for (int j = 0; j < 8; j++) acc[i][j] = 0.f;

    const float cap_mul = (1.0f / 11.3137084989847603904f) / SOFTCAP; // scale/30
    int nkt = (q0 + BQ + BKT - 1) / BKT;

    for (int kt = 0; kt < nkt; kt++) {
        int k0 = kt * BKT;
        __syncthreads();   // previous iter's PV done (also covers Q load, Ls init)

        // --- load K tile transposed, V tile straight (both contiguous in gmem) ---
        const float* Ksrc = Kg + ((size_t)b * Tseq + k0) * KD;
        const float* Vsrc = Vg + ((size_t)b * Tseq + k0) * KD;
#pragma unroll
        for (int i = 0; i < 16; i++) {
            int j = tid + i * 256;      // 0..4095 float4 units
            int r = j >> 5;
            int s = j & 31;
            float4 v = *(const float4*)&Ksrc[(size_t)j * 4];
            int d = s * 4;
            Kst[(d + 0) * SK + r] = v.x; Kst[(d + 1) * SK + r] = v.y;
            Kst[(d + 2) * SK + r] = v.z; Kst[(d + 3) * SK + r] = v.w;
            *(float4*)&Vs[(size_t)j * 4] = *(const float4*)&Vsrc[(size_t)j * 4];
        }
        __syncthreads();

        // --- S = Q @ K^T (64 x 128), softcap+mask+exp, write Pst (k-major) ---
        float sv[4][8];
#pragma unroll
        for (int i = 0; i < 4; i++)
#pragma unroll
            for (int j = 0; j < 8; j++) sv[i][j] = 0.f;

#pragma unroll 4
        for (int kk = 0; kk < HD; kk++) {
            float qv[4], kv[8];
#pragma unroll
            for (int i = 0; i < 4; i++) qv[i] = Qst[kk * SQ + 4 * rg + i];
#pragma unroll
            for (int j = 0; j < 8; j++) kv[j] = Kst[kk * SK + cg + 16 * j];
#pragma unroll
            for (int i = 0; i < 4; i++)
#pragma unroll
                for (int j = 0; j < 8; j++)
                    sv[i][j] += qv[i] * kv[j];
        }

        float rowsum[4] = {0.f, 0.f, 0.f, 0.f};
#pragma unroll
        for (int i = 0; i < 4; i++) {
            int qg = q0 + 4 * rg + i;
#pragma unroll
            for (int j = 0; j < 8; j++) {
                int kgi = k0 + cg + 16 * j;
                float p = 0.f;
                if (kgi <= qg) {
                    float tcap = SOFTCAP * tanhf(sv[i][j] * cap_mul);
                    p = __expf(tcap);
                }
                Pst[(cg + 16 * j) * SP + 4 * rg + i] = p;
                rowsum[i] += p;
            }
        }
        // reduce rowsum across the 16 cg lanes (lane bits 0..3 = cg)
#pragma unroll
        for (int m = 1; m < 16; m <<= 1) {
#pragma unroll
            for (int i = 0; i < 4; i++)
                rowsum[i] += __shfl_xor_sync(0xffffffffu, rowsum[i], m);
        }
        if (cg == 0) {
#pragma unroll
            for (int i = 0; i < 4; i++)
                Ls[4 * rg + i] += rowsum[i];
        }
        __syncthreads();

        // --- acc += P @ V (64 x 128) ---
#pragma unroll 4
        for (int kk = 0; kk < BKT; kk++) {
            float pv[4], vv[8];
#pragma unroll
            for (int i = 0; i < 4; i++) pv[i] = Pst[kk * SP + 4 * rg + i];
#pragma unroll
            for (int j = 0; j < 8; j++) vv[j] = Vs[kk * SV + cg + 16 * j];
#pragma unroll
            for (int i = 0; i < 4; i++)
#pragma unroll
                for (int j = 0; j < 8; j++)
                    acc[i][j] += pv[i] * vv[j];
        }
    }
    __syncthreads();  // Ls final

    // --- epilogue: divide by row sum, write AO[b*T+q, h*128 + col] ---
#pragma unroll
    for (int i = 0; i < 4; i++) {
        float inv = 1.f / Ls[4 * rg + i];
        size_t row = ((size_t)b * Tseq + q0 + 4 * rg + i) * Dm + h * HD;
#pragma unroll
        for (int j = 0; j < 8; j++)
            AO[row + cg + 16 * j] = acc[i][j] * inv;
    }
}

// ---------------------------------------------------------------------------
extern "C" void kernel_launch(void* const* d_in, const int* in_sizes, int n_in,
                              void* d_out, int out_size)
{
    const float* x    = (const float*)d_in[0];
    const float* Wq   = (const float*)d_in[1];
    const float* Wk   = (const float*)d_in[2];
    const float* Wv   = (const float*)d_in[3];
    const float* Wo   = (const float*)d_in[4];
    const float* gain = (const float*)d_in[5];
    const float* cosb = (const float*)d_in[6];
    const float* sinb = (const float*)d_in[7];
    float* out = (float*)d_out;

    float *Q, *K, *V, *AO;
    cudaGetSymbolAddress((void**)&Q, g_Q);
    cudaGetSymbolAddress((void**)&K, g_K);
    cudaGetSymbolAddress((void**)&V, g_V);
    cudaGetSymbolAddress((void**)&AO, g_AO);

    const int M = Bx * Tseq;   // 8192

    // QKV projections
    gemm_nt_kernel<<<dim3(Dm / 128, M / 128), 256>>>(x, Wq, Q, M, Dm, Dm);
    gemm_nt_kernel<<<dim3(KD / 128, M / 128), 256>>>(x, Wk, K, M, KD, Dm);
    gemm_nt_kernel<<<dim3(KD / 128, M / 128), 256>>>(x, Wv, V, M, KD, Dm);

    // RoPE (+ gain for Q)
    rope_q_kernel<<<(Bx * Tseq * NH * 64) / 256, 256>>>(Q, cosb, sinb, gain);
    rope_k_kernel<<<(Bx * Tseq * 64) / 256, 256>>>(K, cosb, sinb);

    // Attention
    size_t smem_bytes = (size_t)ATTN_SMEM_FLOATS * sizeof(float);
    cudaFuncSetAttribute(attn_kernel, cudaFuncAttributeMaxDynamicSharedMemorySize,
                         (int)smem_bytes);
    attn_kernel<<<dim3(Tseq / BQ, NH, Bx), 256, smem_bytes>>>(Q, K, V, AO);

    // Output projection -> d_out
    gemm_nt_kernel<<<dim3(Dm / 128, M / 128), 256>>>(AO, Wo, out, M, Dm, Dm);
}

// round 4
// speedup vs baseline: 1.3291x; 1.3291x over previous
#include <cuda_runtime.h>
#include <cuda_bf16.h>
#include <math.h>
#include <cstdint>

// Problem constants
#define Bx 4
#define Tseq 2048
#define Dm 1024
#define NH 8
#define HD 128
#define SOFTCAP 30.0f
#define MTOT (Bx * Tseq)          // 8192
#define NQKV 1280                 // 1024 Q + 128 K + 128 V fused
#define NWROWS 2304               // 1280 + 1024 (Wo)

// ---------------------------------------------------------------------------
// Scratch (device globals; no allocation allowed)
// ---------------------------------------------------------------------------
__device__ __nv_bfloat16 g_xhi[(size_t)MTOT * Dm];
__device__ __nv_bfloat16 g_xlo[(size_t)MTOT * Dm];
__device__ __nv_bfloat16 g_Whi[(size_t)NWROWS * Dm];
__device__ __nv_bfloat16 g_Wlo[(size_t)NWROWS * Dm];
__device__ float g_QKV[(size_t)MTOT * NQKV];   // 40MB: [q 1024 | k 128 | v 128] per row
__device__ float g_AO[(size_t)MTOT * Dm];      // 32MB attention output
__device__ __nv_bfloat16 g_AOhi[(size_t)MTOT * Dm];
__device__ __nv_bfloat16 g_AOlo[(size_t)MTOT * Dm];

// ---------------------------------------------------------------------------
// helpers
// ---------------------------------------------------------------------------
__device__ __forceinline__ uint32_t smem_u32(const void* p) {
    uint32_t a;
    asm("{ .reg .u64 t; cvta.to.shared.u64 t, %1; cvt.u32.u64 %0, t; }" : "=r"(a) : "l"(p));
    return a;
}
__device__ __forceinline__ void cpa16(uint32_t s, const void* g) {
    asm volatile("cp.async.cg.shared.global [%0], [%1], 16;" :: "r"(s), "l"(g));
}
__device__ __forceinline__ void ldsm4(uint32_t* r, uint32_t a) {
    asm volatile("ldmatrix.sync.aligned.m8n8.x4.shared.b16 {%0,%1,%2,%3}, [%4];"
        : "=r"(r[0]), "=r"(r[1]), "=r"(r[2]), "=r"(r[3]) : "r"(a));
}
__device__ __forceinline__ void mma16816(float* d, const uint32_t* a, const uint32_t* b) {
    asm volatile("mma.sync.aligned.m16n8k16.row.col.f32.bf16.bf16.f32 "
        "{%0,%1,%2,%3}, {%4,%5,%6,%7}, {%8,%9}, {%0,%1,%2,%3};"
        : "+f"(d[0]), "+f"(d[1]), "+f"(d[2]), "+f"(d[3])
        : "r"(a[0]), "r"(a[1]), "r"(a[2]), "r"(a[3]), "r"(b[0]), "r"(b[1]));
}

// ---------------------------------------------------------------------------
// split fp32 -> (hi, lo) bf16
// ---------------------------------------------------------------------------
__global__ void split_kernel(const float* __restrict__ src,
                             __nv_bfloat16* __restrict__ hi,
                             __nv_bfloat16* __restrict__ lo, int n)
{
    int i = (blockIdx.x * blockDim.x + threadIdx.x) * 4;
    if (i >= n) return;
    float4 v = *(const float4*)&src[i];
    __nv_bfloat16 h[4], l[4];
    float vv[4] = {v.x, v.y, v.z, v.w};
#pragma unroll
    for (int j = 0; j < 4; j++) {
        h[j] = __float2bfloat16(vv[j]);
        l[j] = __float2bfloat16(vv[j] - __bfloat162float(h[j]));
    }
    *(uint2*)&hi[i] = *(uint2*)h;
    *(uint2*)&lo[i] = *(uint2*)l;
}

// ---------------------------------------------------------------------------
// HMMA GEMM: C[M, ldc] tile[m0:+128, n0:+128] = A[128,1024] @ B[128,1024]^T
// with split-bf16: C = Ahi Bhi^T + Ahi Blo^T + Alo Bhi^T.
// 256 threads (8 warps: 4m x 2n), warp tile 32x64, BK=32, double-buffered
// cp.async. smem rows padded to 80B -> conflict-free ldmatrix.
// ---------------------------------------------------------------------------
#define GBK 32
#define NCHUNK (Dm / GBK)          // 32
#define ASTRIDE 80                 // bytes per 32-bf16 row (padded from 64)
#define TILE_B (128 * ASTRIDE)     // 10240
#define STAGE_B (4 * TILE_B)       // 40960: Ahi | Alo | Bhi | Blo
#define GEMM_SMEM (2 * STAGE_B)    // 81920

__device__ __forceinline__ void gemm_load_chunk(
    uint32_t sbase, const __nv_bfloat16* gAh, const __nv_bfloat16* gAl,
    const __nv_bfloat16* gBh, const __nv_bfloat16* gBl, int tid, int c)
{
    uint32_t st = sbase + (c & 1) * STAGE_B;
    int k0 = c * GBK;
    const __nv_bfloat16* gp[4] = {gAh, gAl, gBh, gBl};
#pragma unroll
    for (int t = 0; t < 4; t++) {
#pragma unroll
        for (int i = 0; i < 2; i++) {
            int j = tid + i * 256;          // 0..511
            int row = j >> 2, cc = j & 3;
            cpa16(st + t * TILE_B + row * ASTRIDE + cc * 16,
                  gp[t] + (size_t)row * Dm + k0 + cc * 8);
        }
    }
    asm volatile("cp.async.commit_group;" ::: "memory");
}

__global__ __launch_bounds__(256, 1)
void gemm_hmma_kernel(const __nv_bfloat16* __restrict__ Ahi,
                      const __nv_bfloat16* __restrict__ Alo,
                      const __nv_bfloat16* __restrict__ Bhi,
                      const __nv_bfloat16* __restrict__ Blo,
                      float* __restrict__ C, int ldc)
{
    extern __shared__ char smem[];
    uint32_t sbase = smem_u32(smem);
    int tid = threadIdx.x, lane = tid & 31, wid = tid >> 5;
    int wm = wid & 3, wn = wid >> 2;           // warp tile: rows wm*32, cols wn*64
    int n0 = blockIdx.x * 128, m0 = blockIdx.y * 128;

    const __nv_bfloat16* gAh = Ahi + (size_t)m0 * Dm;
    const __nv_bfloat16* gAl = Alo + (size_t)m0 * Dm;
    const __nv_bfloat16* gBh = Bhi + (size_t)n0 * Dm;
    const __nv_bfloat16* gBl = Blo + (size_t)n0 * Dm;

    float acc[16][4];
#pragma unroll
    for (int f = 0; f < 16; f++)
#pragma unroll
        for (int j = 0; j < 4; j++) acc[f][j] = 0.f;

    gemm_load_chunk(sbase, gAh, gAl, gBh, gBl, tid, 0);
    gemm_load_chunk(sbase, gAh, gAl, gBh, gBl, tid, 1);

    // precomputed intra-tile ldmatrix offsets
    uint32_t a_off = (wm * 32 + (lane & 15)) * ASTRIDE + (lane >> 4) * 16;
    uint32_t b_off = (wn * 64 + (lane & 7) + ((lane >> 4) << 3)) * ASTRIDE
                   + ((lane >> 3) & 1) * 16;

    for (int c = 0; c < NCHUNK; c++) {
        if (c + 1 < NCHUNK)
            asm volatile("cp.async.wait_group 1;" ::: "memory");
        else
            asm volatile("cp.async.wait_group 0;" ::: "memory");
        __syncthreads();

        uint32_t st = sbase + (c & 1) * STAGE_B;
#pragma unroll
        for (int ks = 0; ks < 2; ks++) {
            uint32_t ah[2][4], al[2][4], bh[8][2], bl[8][2];
#pragma unroll
            for (int mi = 0; mi < 2; mi++) {
                uint32_t addr = st + a_off + mi * 16 * ASTRIDE + ks * 32;
                ldsm4(ah[mi], addr);
                ldsm4(al[mi], addr + TILE_B);
            }
#pragma unroll
            for (int nf2 = 0; nf2 < 4; nf2++) {
                uint32_t addr = st + 2 * TILE_B + b_off + nf2 * 16 * ASTRIDE + ks * 32;
                uint32_t r[4];
                ldsm4(r, addr);
                bh[2 * nf2][0] = r[0]; bh[2 * nf2][1] = r[1];
                bh[2 * nf2 + 1][0] = r[2]; bh[2 * nf2 + 1][1] = r[3];
                ldsm4(r, addr + TILE_B);
                bl[2 * nf2][0] = r[0]; bl[2 * nf2][1] = r[1];
                bl[2 * nf2 + 1][0] = r[2]; bl[2 * nf2 + 1][1] = r[3];
            }
#pragma unroll
            for (int mi = 0; mi < 2; mi++)
#pragma unroll
                for (int nf = 0; nf < 8; nf++) {
                    float* d = acc[mi * 8 + nf];
                    mma16816(d, ah[mi], bh[nf]);
                    mma16816(d, ah[mi], bl[nf]);
                    mma16816(d, al[mi], bh[nf]);
                }
        }
        __syncthreads();
        if (c + 2 < NCHUNK)
            gemm_load_chunk(sbase, gAh, gAl, gBh, gBl, tid, c + 2);
    }

    // epilogue: c0,c1 -> row l>>2, cols (l&3)*2; c2,c3 -> row +8
#pragma unroll
    for (int mi = 0; mi < 2; mi++)
#pragma unroll
        for (int nf = 0; nf < 8; nf++) {
            float* d = acc[mi * 8 + nf];
            size_t row = (size_t)(m0 + wm * 32 + mi * 16 + (lane >> 2));
            float* cp = C + row * ldc + n0 + wn * 64 + nf * 8 + (lane & 3) * 2;
            *(float2*)cp = make_float2(d[0], d[1]);
            *(float2*)(cp + 8 * (size_t)ldc) = make_float2(d[2], d[3]);
        }
}

// ---------------------------------------------------------------------------
// RoPE on fused QKV buffer. Q cols [0,1024), K cols [1024,1152). stride 1280.
// ---------------------------------------------------------------------------
__global__ void rope_q_kernel(float* __restrict__ QKV,
                              const float* __restrict__ cosb,
                              const float* __restrict__ sinb,
                              const float* __restrict__ gain)
{
    int idx = blockIdx.x * blockDim.x + threadIdx.x;   // B*T*NH*64
    if (idx >= Bx * Tseq * NH * 64) return;
    int d = idx & 63;
    int h = (idx >> 6) & (NH - 1);
    int bt = idx >> 9;
    int t = bt & (Tseq - 1);
    size_t base = (size_t)bt * NQKV + h * HD + d;
    float x1 = QKV[base], x2 = QKV[base + 64];
    float c = cosb[t * 64 + d], s = sinb[t * 64 + d];
    float g = gain[h];
    QKV[base]      = (x1 * c - x2 * s) * g;
    QKV[base + 64] = (x1 * s + x2 * c) * g;
}

__global__ void rope_k_kernel(float* __restrict__ QKV,
                              const float* __restrict__ cosb,
                              const float* __restrict__ sinb)
{
    int idx = blockIdx.x * blockDim.x + threadIdx.x;   // B*T*64
    if (idx >= Bx * Tseq * 64) return;
    int d = idx & 63;
    int bt = idx >> 6;
    int t = bt & (Tseq - 1);
    size_t base = (size_t)bt * NQKV + 1024 + d;
    float x1 = QKV[base], x2 = QKV[base + 64];
    float c = cosb[t * 64 + d], s = sinb[t * 64 + d];
    QKV[base]      = x1 * c - x2 * s;
    QKV[base + 64] = x1 * s + x2 * c;
}

// ---------------------------------------------------------------------------
// Flash-style causal attention with softcap (fp32 SIMT). Reads fused QKV.
// Softcapped scores bounded by 30 -> no online max needed.
// ---------------------------------------------------------------------------
#define BQ 64
#define BKT 128
#define SQ 65
#define SK 129
#define SV 128
#define SP 65
#define ATTN_SMEM_FLOATS (HD*SQ + HD*SK + BKT*SV + BKT*SP + BQ)

__global__ __launch_bounds__(256) void attn_kernel(
    const float* __restrict__ QKV, float* __restrict__ AO)
{
    extern __shared__ float sm[];
    float* Qst = sm;
    float* Kst = Qst + HD * SQ;
    float* Vs  = Kst + HD * SK;
    float* Pst = Vs + BKT * SV;
    float* Ls  = Pst + BKT * SP;

    int q0 = blockIdx.x * BQ;
    int h  = blockIdx.y;
    int b  = blockIdx.z;
    int tid = threadIdx.x;
    int rg = tid >> 4;
    int cg = tid & 15;

    const size_t qbase = ((size_t)b * Tseq + q0) * NQKV + h * HD;
#pragma unroll
    for (int i = 0; i < 8; i++) {
        int j = tid + i * 256;
        int r = j >> 5;
        int s = j & 31;
        float4 v = *(const float4*)&QKV[qbase + (size_t)r * NQKV + s * 4];
        int d = s * 4;
        Qst[(d + 0) * SQ + r] = v.x; Qst[(d + 1) * SQ + r] = v.y;
        Qst[(d + 2) * SQ + r] = v.z; Qst[(d + 3) * SQ + r] = v.w;
    }
    if (tid < BQ) Ls[tid] = 0.f;

    float acc[4][8];
#pragma unroll
    for (int i = 0; i < 4; i++)
#pragma unroll
        for (int j = 0; j < 8; j++) acc[i][j] = 0.f;

    const float cap_mul = (1.0f / 11.3137084989847603904f) / SOFTCAP;
    int nkt = (q0 + BQ + BKT - 1) / BKT;

    for (int kt = 0; kt < nkt; kt++) {
        int k0 = kt * BKT;
        __syncthreads();

        const float* Ksrc = QKV + ((size_t)b * Tseq + k0) * NQKV + 1024;
        const float* Vsrc = QKV + ((size_t)b * Tseq + k0) * NQKV + 1152;
#pragma unroll
        for (int i = 0; i < 16; i++) {
            int j = tid + i * 256;
            int r = j >> 5;
            int s = j & 31;
            float4 v = *(const float4*)&Ksrc[(size_t)r * NQKV + s * 4];
            int d = s * 4;
            Kst[(d + 0) * SK + r] = v.x; Kst[(d + 1) * SK + r] = v.y;
            Kst[(d + 2) * SK + r] = v.z; Kst[(d + 3) * SK + r] = v.w;
            *(float4*)&Vs[r * SV + s * 4] = *(const float4*)&Vsrc[(size_t)r * NQKV + s * 4];
        }
        __syncthreads();

        float sv[4][8];
#pragma unroll
        for (int i = 0; i < 4; i++)
#pragma unroll
            for (int j = 0; j < 8; j++) sv[i][j] = 0.f;

#pragma unroll 4
        for (int kk = 0; kk < HD; kk++) {
            float qv[4], kv[8];
#pragma unroll
            for (int i = 0; i < 4; i++) qv[i] = Qst[kk * SQ + 4 * rg + i];
#pragma unroll
            for (int j = 0; j < 8; j++) kv[j] = Kst[kk * SK + cg + 16 * j];
#pragma unroll
            for (int i = 0; i < 4; i++)
#pragma unroll
                for (int j = 0; j < 8; j++)
                    sv[i][j] += qv[i] * kv[j];
        }

        float rowsum[4] = {0.f, 0.f, 0.f, 0.f};
#pragma unroll
        for (int i = 0; i < 4; i++) {
            int qg = q0 + 4 * rg + i;
#pragma unroll
            for (int j = 0; j < 8; j++) {
                int kgi = k0 + cg + 16 * j;
                float p = 0.f;
                if (kgi <= qg) {
                    // tanh via exp: tanh(y) = 1 - 2/(e^{2y}+1)
                    float y = sv[i][j] * cap_mul;
                    float t = __expf(2.f * y);
                    float tcap = SOFTCAP * (1.f - 2.f / (t + 1.f));
                    p = __expf(tcap);
                }
                Pst[(cg + 16 * j) * SP + 4 * rg + i] = p;
                rowsum[i] += p;
            }
        }
#pragma unroll
        for (int m = 1; m < 16; m <<= 1) {
#pragma unroll
            for (int i = 0; i < 4; i++)
                rowsum[i] += __shfl_xor_sync(0xffffffffu, rowsum[i], m);
        }
        if (cg == 0) {
#pragma unroll
            for (int i = 0; i < 4; i++)
                Ls[4 * rg + i] += rowsum[i];
        }
        __syncthreads();

#pragma unroll 4
        for (int kk = 0; kk < BKT; kk++) {
            float pv[4], vv[8];
#pragma unroll
            for (int i = 0; i < 4; i++) pv[i] = Pst[kk * SP + 4 * rg + i];
#pragma unroll
            for (int j = 0; j < 8; j++) vv[j] = Vs[kk * SV + cg + 16 * j];
#pragma unroll
            for (int i = 0; i < 4; i++)
#pragma unroll
                for (int j = 0; j < 8; j++)
                    acc[i][j] += pv[i] * vv[j];
        }
    }
    __syncthreads();

#pragma unroll
    for (int i = 0; i < 4; i++) {
        float inv = 1.f / Ls[4 * rg + i];
        size_t row = ((size_t)b * Tseq + q0 + 4 * rg + i) * Dm + h * HD;
#pragma unroll
        for (int j = 0; j < 8; j++)
            AO[row + cg + 16 * j] = acc[i][j] * inv;
    }
}

// ---------------------------------------------------------------------------
extern "C" void kernel_launch(void* const* d_in, const int* in_sizes, int n_in,
                              void* d_out, int out_size)
{
    const float* x    = (const float*)d_in[0];
    const float* Wq   = (const float*)d_in[1];
    const float* Wk   = (const float*)d_in[2];
    const float* Wv   = (const float*)d_in[3];
    const float* Wo   = (const float*)d_in[4];
    const float* gain = (const float*)d_in[5];
    const float* cosb = (const float*)d_in[6];
    const float* sinb = (const float*)d_in[7];
    float* out = (float*)d_out;

    __nv_bfloat16 *xhi, *xlo, *Whi, *Wlo, *AOhi, *AOlo;
    float *QKV, *AO;
    cudaGetSymbolAddress((void**)&xhi, g_xhi);
    cudaGetSymbolAddress((void**)&xlo, g_xlo);
    cudaGetSymbolAddress((void**)&Whi, g_Whi);
    cudaGetSymbolAddress((void**)&Wlo, g_Wlo);
    cudaGetSymbolAddress((void**)&QKV, g_QKV);
    cudaGetSymbolAddress((void**)&AO, g_AO);
    cudaGetSymbolAddress((void**)&AOhi, g_AOhi);
    cudaGetSymbolAddress((void**)&AOlo, g_AOlo);

    const int nx = MTOT * Dm;          // 8.39M

    // split inputs to (hi, lo) bf16
    split_kernel<<<nx / 4 / 256, 256>>>(x, xhi, xlo, nx);
    split_kernel<<<(1024 * Dm) / 4 / 256, 256>>>(Wq, Whi, Wlo, 1024 * Dm);
    split_kernel<<<(128 * Dm) / 4 / 256, 256>>>(Wk, Whi + (size_t)1024 * Dm, Wlo + (size_t)1024 * Dm, 128 * Dm);
    split_kernel<<<(128 * Dm) / 4 / 256, 256>>>(Wv, Whi + (size_t)1152 * Dm, Wlo + (size_t)1152 * Dm, 128 * Dm);
    split_kernel<<<(1024 * Dm) / 4 / 256, 256>>>(Wo, Whi + (size_t)1280 * Dm, Wlo + (size_t)1280 * Dm, 1024 * Dm);

    cudaFuncSetAttribute(gemm_hmma_kernel, cudaFuncAttributeMaxDynamicSharedMemorySize, GEMM_SMEM);

    // fused QKV projection
    gemm_hmma_kernel<<<dim3(NQKV / 128, MTOT / 128), 256, GEMM_SMEM>>>(
        xhi, xlo, Whi, Wlo, QKV, NQKV);

    // RoPE (+ gain for Q)
    rope_q_kernel<<<(Bx * Tseq * NH * 64) / 256, 256>>>(QKV, cosb, sinb, gain);
    rope_k_kernel<<<(Bx * Tseq * 64) / 256, 256>>>(QKV, cosb, sinb);

    // Attention
    size_t smem_bytes = (size_t)ATTN_SMEM_FLOATS * sizeof(float);
    cudaFuncSetAttribute(attn_kernel, cudaFuncAttributeMaxDynamicSharedMemorySize, (int)smem_bytes);
    attn_kernel<<<dim3(Tseq / BQ, NH, Bx), 256, smem_bytes>>>(QKV, AO);

    // split AO, output projection
    split_kernel<<<nx / 4 / 256, 256>>>(AO, AOhi, AOlo, nx);
    gemm_hmma_kernel<<<dim3(Dm / 128, MTOT / 128), 256, GEMM_SMEM>>>(
        AOhi, AOlo, Whi + (size_t)1280 * Dm, Wlo + (size_t)1280 * Dm, out, Dm);
}

// round 6
// speedup vs baseline: 2.4872x; 1.8714x over previous
#include <cuda_runtime.h>
#include <cuda_bf16.h>
#include <math.h>
#include <cstdint>

// Problem constants
#define Bx 4
#define Tseq 2048
#define Dm 1024
#define NH 8
#define HD 128
#define SOFTCAP 30.0f
#define MTOT (Bx * Tseq)          // 8192
#define NQKV 1280                 // 1024 Q + 128 K + 128 V fused
#define NWROWS 2304               // 1280 + 1024 (Wo)

// ---------------------------------------------------------------------------
// Scratch (device globals; no allocation allowed)
// ---------------------------------------------------------------------------
__device__ __nv_bfloat16 g_xhi[(size_t)MTOT * Dm];
__device__ __nv_bfloat16 g_xlo[(size_t)MTOT * Dm];
__device__ __nv_bfloat16 g_Whi[(size_t)NWROWS * Dm];
__device__ __nv_bfloat16 g_Wlo[(size_t)NWROWS * Dm];
__device__ float g_QKV[(size_t)MTOT * NQKV];   // 40MB GEMM output
__device__ __nv_bfloat16 g_Qhi[(size_t)MTOT * Dm];
__device__ __nv_bfloat16 g_Qlo[(size_t)MTOT * Dm];
__device__ __nv_bfloat16 g_Khi[(size_t)MTOT * HD];
__device__ __nv_bfloat16 g_Klo[(size_t)MTOT * HD];
__device__ __nv_bfloat16 g_Vhi[(size_t)MTOT * HD];
__device__ __nv_bfloat16 g_Vlo[(size_t)MTOT * HD];
__device__ __nv_bfloat16 g_AOhi[(size_t)MTOT * Dm];
__device__ __nv_bfloat16 g_AOlo[(size_t)MTOT * Dm];

// ---------------------------------------------------------------------------
// helpers
// ---------------------------------------------------------------------------
__device__ __forceinline__ uint32_t smem_u32(const void* p) {
    uint32_t a;
    asm("{ .reg .u64 t; cvta.to.shared.u64 t, %1; cvt.u32.u64 %0, t; }" : "=r"(a) : "l"(p));
    return a;
}
__device__ __forceinline__ void cpa16(uint32_t s, const void* g) {
    asm volatile("cp.async.cg.shared.global [%0], [%1], 16;" :: "r"(s), "l"(g));
}
__device__ __forceinline__ void ldsm4(uint32_t* r, uint32_t a) {
    asm volatile("ldmatrix.sync.aligned.m8n8.x4.shared.b16 {%0,%1,%2,%3}, [%4];"
        : "=r"(r[0]), "=r"(r[1]), "=r"(r[2]), "=r"(r[3]) : "r"(a));
}
__device__ __forceinline__ void ldsm4t(uint32_t* r, uint32_t a) {
    asm volatile("ldmatrix.sync.aligned.m8n8.x4.trans.shared.b16 {%0,%1,%2,%3}, [%4];"
        : "=r"(r[0]), "=r"(r[1]), "=r"(r[2]), "=r"(r[3]) : "r"(a));
}
__device__ __forceinline__ void mma16816(float* d, const uint32_t* a, const uint32_t* b) {
    asm volatile("mma.sync.aligned.m16n8k16.row.col.f32.bf16.bf16.f32 "
        "{%0,%1,%2,%3}, {%4,%5,%6,%7}, {%8,%9}, {%0,%1,%2,%3};"
        : "+f"(d[0]), "+f"(d[1]), "+f"(d[2]), "+f"(d[3])
        : "r"(a[0]), "r"(a[1]), "r"(a[2]), "r"(a[3]), "r"(b[0]), "r"(b[1]));
}
__device__ __forceinline__ uint16_t bf16_bits(float x) {
    __nv_bfloat16 h = __float2bfloat16(x);
    return *(uint16_t*)&h;
}
// split two floats into packed (hi, lo) bf16x2 registers
__device__ __forceinline__ void split_pack2(float x, float y, uint32_t& hi, uint32_t& lo) {
    __nv_bfloat16 xh = __float2bfloat16(x), yh = __float2bfloat16(y);
    float xr = x - __bfloat162float(xh), yr = y - __bfloat162float(yh);
    __nv_bfloat16 xl = __float2bfloat16(xr), yl = __float2bfloat16(yr);
    hi = (uint32_t)(*(uint16_t*)&xh) | ((uint32_t)(*(uint16_t*)&yh) << 16);
    lo = (uint32_t)(*(uint16_t*)&xl) | ((uint32_t)(*(uint16_t*)&yl) << 16);
}

// ---------------------------------------------------------------------------
// split fp32 -> (hi, lo) bf16
// ---------------------------------------------------------------------------
__global__ void split_kernel(const float* __restrict__ src,
                             __nv_bfloat16* __restrict__ hi,
                             __nv_bfloat16* __restrict__ lo, int n)
{
    int i = (blockIdx.x * blockDim.x + threadIdx.x) * 4;
    if (i >= n) return;
    float4 v = *(const float4*)&src[i];
    __nv_bfloat16 h[4], l[4];
    float vv[4] = {v.x, v.y, v.z, v.w};
#pragma unroll
    for (int j = 0; j < 4; j++) {
        h[j] = __float2bfloat16(vv[j]);
        l[j] = __float2bfloat16(vv[j] - __bfloat162float(h[j]));
    }
    *(uint2*)&hi[i] = *(uint2*)h;
    *(uint2*)&lo[i] = *(uint2*)l;
}

// ---------------------------------------------------------------------------
// HMMA GEMM (same as R4): C tile = A[128,1024] @ B[128,1024]^T, split bf16.
// ---------------------------------------------------------------------------
#define GBK 32
#define NCHUNK (Dm / GBK)          // 32
#define ASTRIDE 80
#define TILE_B (128 * ASTRIDE)
#define STAGE_B (4 * TILE_B)
#define GEMM_SMEM (2 * STAGE_B)

__device__ __forceinline__ void gemm_load_chunk(
    uint32_t sbase, const __nv_bfloat16* gAh, const __nv_bfloat16* gAl,
    const __nv_bfloat16* gBh, const __nv_bfloat16* gBl, int tid, int c)
{
    uint32_t st = sbase + (c & 1) * STAGE_B;
    int k0 = c * GBK;
    const __nv_bfloat16* gp[4] = {gAh, gAl, gBh, gBl};
#pragma unroll
    for (int t = 0; t < 4; t++) {
#pragma unroll
        for (int i = 0; i < 2; i++) {
            int j = tid + i * 256;
            int row = j >> 2, cc = j & 3;
            cpa16(st + t * TILE_B + row * ASTRIDE + cc * 16,
                  gp[t] + (size_t)row * Dm + k0 + cc * 8);
        }
    }
    asm volatile("cp.async.commit_group;" ::: "memory");
}

__global__ __launch_bounds__(256, 1)
void gemm_hmma_kernel(const __nv_bfloat16* __restrict__ Ahi,
                      const __nv_bfloat16* __restrict__ Alo,
                      const __nv_bfloat16* __restrict__ Bhi,
                      const __nv_bfloat16* __restrict__ Blo,
                      float* __restrict__ C, int ldc)
{
    extern __shared__ char smem[];
    uint32_t sbase = smem_u32(smem);
    int tid = threadIdx.x, lane = tid & 31, wid = tid >> 5;
    int wm = wid & 3, wn = wid >> 2;
    int n0 = blockIdx.x * 128, m0 = blockIdx.y * 128;

    const __nv_bfloat16* gAh = Ahi + (size_t)m0 * Dm;
    const __nv_bfloat16* gAl = Alo + (size_t)m0 * Dm;
    const __nv_bfloat16* gBh = Bhi + (size_t)n0 * Dm;
    const __nv_bfloat16* gBl = Blo + (size_t)n0 * Dm;

    float acc[16][4];
#pragma unroll
    for (int f = 0; f < 16; f++)
#pragma unroll
        for (int j = 0; j < 4; j++) acc[f][j] = 0.f;

    gemm_load_chunk(sbase, gAh, gAl, gBh, gBl, tid, 0);
    gemm_load_chunk(sbase, gAh, gAl, gBh, gBl, tid, 1);

    uint32_t a_off = (wm * 32 + (lane & 15)) * ASTRIDE + (lane >> 4) * 16;
    uint32_t b_off = (wn * 64 + (lane & 7) + ((lane >> 4) << 3)) * ASTRIDE
                   + ((lane >> 3) & 1) * 16;

    for (int c = 0; c < NCHUNK; c++) {
        if (c + 1 < NCHUNK)
            asm volatile("cp.async.wait_group 1;" ::: "memory");
        else
            asm volatile("cp.async.wait_group 0;" ::: "memory");
        __syncthreads();

        uint32_t st = sbase + (c & 1) * STAGE_B;
#pragma unroll
        for (int ks = 0; ks < 2; ks++) {
            uint32_t ah[2][4], al[2][4], bh[8][2], bl[8][2];
#pragma unroll
            for (int mi = 0; mi < 2; mi++) {
                uint32_t addr = st + a_off + mi * 16 * ASTRIDE + ks * 32;
                ldsm4(ah[mi], addr);
                ldsm4(al[mi], addr + TILE_B);
            }
#pragma unroll
            for (int nf2 = 0; nf2 < 4; nf2++) {
                uint32_t addr = st + 2 * TILE_B + b_off + nf2 * 16 * ASTRIDE + ks * 32;
                uint32_t r[4];
                ldsm4(r, addr);
                bh[2 * nf2][0] = r[0]; bh[2 * nf2][1] = r[1];
                bh[2 * nf2 + 1][0] = r[2]; bh[2 * nf2 + 1][1] = r[3];
                ldsm4(r, addr + TILE_B);
                bl[2 * nf2][0] = r[0]; bl[2 * nf2][1] = r[1];
                bl[2 * nf2 + 1][0] = r[2]; bl[2 * nf2 + 1][1] = r[3];
            }
#pragma unroll
            for (int mi = 0; mi < 2; mi++)
#pragma unroll
                for (int nf = 0; nf < 8; nf++) {
                    float* d = acc[mi * 8 + nf];
                    mma16816(d, ah[mi], bh[nf]);
                    mma16816(d, ah[mi], bl[nf]);
                    mma16816(d, al[mi], bh[nf]);
                }
        }
        __syncthreads();
        if (c + 2 < NCHUNK)
            gemm_load_chunk(sbase, gAh, gAl, gBh, gBl, tid, c + 2);
    }

#pragma unroll
    for (int mi = 0; mi < 2; mi++)
#pragma unroll
        for (int nf = 0; nf < 8; nf++) {
            float* d = acc[mi * 8 + nf];
            size_t row = (size_t)(m0 + wm * 32 + mi * 16 + (lane >> 2));
            float* cp = C + row * ldc + n0 + wn * 64 + nf * 8 + (lane & 3) * 2;
            *(float2*)cp = make_float2(d[0], d[1]);
            *(float2*)(cp + 8 * (size_t)ldc) = make_float2(d[2], d[3]);
        }
}

// ---------------------------------------------------------------------------
// RoPE + split to bf16(hi,lo). Reads fused QKV fp32.
// ---------------------------------------------------------------------------
__global__ void rope_q_split(const float* __restrict__ QKV,
                             const float* __restrict__ cosb,
                             const float* __restrict__ sinb,
                             const float* __restrict__ gain,
                             __nv_bfloat16* __restrict__ Qhi,
                             __nv_bfloat16* __restrict__ Qlo)
{
    int idx = blockIdx.x * blockDim.x + threadIdx.x;   // B*T*NH*64
    if (idx >= Bx * Tseq * NH * 64) return;
    int d = idx & 63;
    int h = (idx >> 6) & (NH - 1);
    int bt = idx >> 9;
    int t = bt & (Tseq - 1);
    size_t src = (size_t)bt * NQKV + h * HD + d;
    float x1 = QKV[src], x2 = QKV[src + 64];
    float c = cosb[t * 64 + d], s = sinb[t * 64 + d];
    float g = gain[h];
    float y1 = (x1 * c - x2 * s) * g;
    float y2 = (x1 * s + x2 * c) * g;
    size_t o = (size_t)bt * Dm + h * HD + d;
    __nv_bfloat16 h1 = __float2bfloat16(y1), h2 = __float2bfloat16(y2);
    Qhi[o] = h1; Qhi[o + 64] = h2;
    Qlo[o] = __float2bfloat16(y1 - __bfloat162float(h1));
    Qlo[o + 64] = __float2bfloat16(y2 - __bfloat162float(h2));
}

__global__ void rope_k_split(const float* __restrict__ QKV,
                             const float* __restrict__ cosb,
                             const float* __restrict__ sinb,
                             __nv_bfloat16* __restrict__ Khi,
                             __nv_bfloat16* __restrict__ Klo)
{
    int idx = blockIdx.x * blockDim.x + threadIdx.x;   // B*T*64
    if (idx >= Bx * Tseq * 64) return;
    int d = idx & 63;
    int bt = idx >> 6;
    int t = bt & (Tseq - 1);
    size_t src = (size_t)bt * NQKV + 1024 + d;
    float x1 = QKV[src], x2 = QKV[src + 64];
    float c = cosb[t * 64 + d], s = sinb[t * 64 + d];
    float y1 = x1 * c - x2 * s;
    float y2 = x1 * s + x2 * c;
    size_t o = (size_t)bt * HD + d;
    __nv_bfloat16 h1 = __float2bfloat16(y1), h2 = __float2bfloat16(y2);
    Khi[o] = h1; Khi[o + 64] = h2;
    Klo[o] = __float2bfloat16(y1 - __bfloat162float(h1));
    Klo[o + 64] = __float2bfloat16(y2 - __bfloat162float(h2));
}

__global__ void v_split(const float* __restrict__ QKV,
                        __nv_bfloat16* __restrict__ Vhi,
                        __nv_bfloat16* __restrict__ Vlo)
{
    int idx = blockIdx.x * blockDim.x + threadIdx.x;   // B*T*128
    if (idx >= Bx * Tseq * HD) return;
    int d = idx & 127;
    int bt = idx >> 7;
    float v = QKV[(size_t)bt * NQKV + 1152 + d];
    __nv_bfloat16 h = __float2bfloat16(v);
    Vhi[idx] = h;
    Vlo[idx] = __float2bfloat16(v - __bfloat162float(h));
}

// ---------------------------------------------------------------------------
// HMMA flash attention, split bf16 (Q,K,P,V all hi+lo, 3-term MMAs).
// Block: (q-tile 64, head, batch), 256 threads = 8 warps (4m x 2n).
// K-tile = 64. smem rows padded to 272B (conflict-free ldmatrix).
// ---------------------------------------------------------------------------
#define KSTR 272
#define ATILE 17408                 // 64 * KSTR
#define ASTAGE (4 * ATILE)          // Khi|Klo|Vhi|Vlo
#define AQ_OFF 0
#define AST_OFF (2 * ATILE)         // 34816
#define ALS_OFF (AST_OFF + 2 * ASTAGE)   // 174080
#define ATTN_SMEM (ALS_OFF + 256)

__device__ __forceinline__ void attn_load_stage(uint32_t st,
    const __nv_bfloat16* kh, const __nv_bfloat16* kl,
    const __nv_bfloat16* vh, const __nv_bfloat16* vl, int tid)
{
#pragma unroll
    for (int i = 0; i < 4; i++) {
        int j = tid + i * 256;
        int row = j >> 4, c = j & 15;
        uint32_t so = row * KSTR + c * 16;
        size_t go = (size_t)row * HD + c * 8;
        cpa16(st + so, kh + go);
        cpa16(st + ATILE + so, kl + go);
        cpa16(st + 2 * ATILE + so, vh + go);
        cpa16(st + 3 * ATILE + so, vl + go);
    }
    asm volatile("cp.async.commit_group;" ::: "memory");
}

__global__ __launch_bounds__(256, 1)
void attn_hmma_kernel(const __nv_bfloat16* __restrict__ Qhi,
                      const __nv_bfloat16* __restrict__ Qlo,
                      const __nv_bfloat16* __restrict__ Khi,
                      const __nv_bfloat16* __restrict__ Klo,
                      const __nv_bfloat16* __restrict__ Vhi,
                      const __nv_bfloat16* __restrict__ Vlo,
                      __nv_bfloat16* __restrict__ AOhi,
                      __nv_bfloat16* __restrict__ AOlo)
{
    extern __shared__ char sm[];
    uint32_t sb = smem_u32(sm);
    float* Ls = (float*)(sm + ALS_OFF);

    int qt = gridDim.x - 1 - blockIdx.x;     // long blocks first
    int h = blockIdx.y, b = blockIdx.z;
    int q0 = qt * 64;
    int tid = threadIdx.x, lane = tid & 31, wid = tid >> 5;
    int wm = wid & 3, wn = wid >> 2;
    int nkt = qt + 1;

    if (tid < 64) Ls[tid] = 0.f;

    // Q tile (hi,lo) via cp.async
    {
        const __nv_bfloat16* qh = Qhi + ((size_t)(b * Tseq + q0)) * Dm + h * HD;
        const __nv_bfloat16* ql = Qlo + ((size_t)(b * Tseq + q0)) * Dm + h * HD;
#pragma unroll
        for (int i = 0; i < 4; i++) {
            int j = tid + i * 256;
            int row = j >> 4, c = j & 15;
            uint32_t so = row * KSTR + c * 16;
            size_t go = (size_t)row * Dm + c * 8;
            cpa16(sb + AQ_OFF + so, qh + go);
            cpa16(sb + AQ_OFF + ATILE + so, ql + go);
        }
        asm volatile("cp.async.commit_group;" ::: "memory");
    }
    {
        size_t base = (size_t)(b * Tseq) * HD;
        attn_load_stage(sb + AST_OFF, Khi + base, Klo + base, Vhi + base, Vlo + base, tid);
        if (nkt > 1) {
            size_t b1 = base + 64 * HD;
            attn_load_stage(sb + AST_OFF + ASTAGE, Khi + b1, Klo + b1, Vhi + b1, Vlo + b1, tid);
        }
    }

    float acc[16][4];
#pragma unroll
    for (int f = 0; f < 16; f++)
#pragma unroll
        for (int j = 0; j < 4; j++) acc[f][j] = 0.f;

    const float cap_mul = 0.0029462782549439483f;   // 1/(sqrt(128)*30)

    // ldmatrix address pieces
    uint32_t aQoff = AQ_OFF + (wm * 16 + (lane & 15)) * KSTR + (lane >> 4) * 16;
    uint32_t bKrow = wn * 32 + (lane & 7) + ((lane >> 4) & 1) * 8;
    uint32_t bKoff = bKrow * KSTR + ((lane >> 3) & 1) * 16;

    for (int kt = 0; kt < nkt; kt++) {
        if (kt + 1 < nkt)
            asm volatile("cp.async.wait_group 1;" ::: "memory");
        else
            asm volatile("cp.async.wait_group 0;" ::: "memory");
        __syncthreads();

        uint32_t stK = sb + AST_OFF + (kt & 1) * ASTAGE;
        uint32_t stV = stK + 2 * ATILE;

        // ---- S = Q K^T (warp tile 16 x 32), 3-term split ----
        float sfrag[4][4];
#pragma unroll
        for (int f = 0; f < 4; f++)
#pragma unroll
            for (int e = 0; e < 4; e++) sfrag[f][e] = 0.f;

#pragma unroll
        for (int kb = 0; kb < 8; kb++) {
            uint32_t ah[4], al[4];
            ldsm4(ah, sb + aQoff + kb * 32);
            ldsm4(al, sb + aQoff + ATILE + kb * 32);
#pragma unroll
            for (int nb = 0; nb < 2; nb++) {
                uint32_t bhh[4], bll[4];
                uint32_t baddr = stK + bKoff + nb * 16 * KSTR + kb * 32;
                ldsm4(bhh, baddr);
                ldsm4(bll, baddr + ATILE);
                mma16816(sfrag[nb * 2],     ah, &bhh[0]);
                mma16816(sfrag[nb * 2],     ah, &bll[0]);
                mma16816(sfrag[nb * 2],     al, &bhh[0]);
                mma16816(sfrag[nb * 2 + 1], ah, &bhh[2]);
                mma16816(sfrag[nb * 2 + 1], ah, &bll[2]);
                mma16816(sfrag[nb * 2 + 1], al, &bhh[2]);
            }
        }

        // ---- softcap + causal mask + exp, rowsum ----
        bool diag = (kt == nkt - 1);
        int rloc = wm * 16 + (lane >> 2);          // local row (first of pair)
        float rs0 = 0.f, rs1 = 0.f;
        float p[4][4];
#pragma unroll
        for (int nf = 0; nf < 4; nf++) {
            int colb = wn * 32 + nf * 8 + 2 * (lane & 3);
#pragma unroll
            for (int e = 0; e < 4; e++) {
                int row = rloc + ((e >> 1) << 3);
                int col = colb + (e & 1);
                float y = sfrag[nf][e] * cap_mul;
                float t = __expf(2.f * y);
                float tc = SOFTCAP * (1.f - 2.f / (t + 1.f));
                float pv = __expf(tc);
                if (diag && col > row) pv = 0.f;
                p[nf][e] = pv;
                if (e < 2) rs0 += pv; else rs1 += pv;
            }
        }
        rs0 += __shfl_xor_sync(0xffffffffu, rs0, 1);
        rs0 += __shfl_xor_sync(0xffffffffu, rs0, 2);
        rs1 += __shfl_xor_sync(0xffffffffu, rs1, 1);
        rs1 += __shfl_xor_sync(0xffffffffu, rs1, 2);
        if ((lane & 3) == 0) {
            atomicAdd(&Ls[rloc], rs0);
            atomicAdd(&Ls[rloc + 8], rs1);
        }

        // ---- P -> A frags (split) ----
        uint32_t aPh[2][4], aPl[2][4];
#pragma unroll
        for (int kb2 = 0; kb2 < 2; kb2++) {
            int j = kb2 * 2;
            split_pack2(p[j][0],     p[j][1],     aPh[kb2][0], aPl[kb2][0]);
            split_pack2(p[j][2],     p[j][3],     aPh[kb2][1], aPl[kb2][1]);
            split_pack2(p[j + 1][0], p[j + 1][1], aPh[kb2][2], aPl[kb2][2]);
            split_pack2(p[j + 1][2], p[j + 1][3], aPh[kb2][3], aPl[kb2][3]);
        }

        // ---- acc += P @ V (k-slice = warp's 32 cols) ----
#pragma unroll
        for (int kb2 = 0; kb2 < 2; kb2++) {
            int t0 = wn * 32 + kb2 * 16;
            uint32_t vAddr0 = stV + (t0 + (lane & 15)) * KSTR + (lane >> 4) * 16;
#pragma unroll
            for (int nb = 0; nb < 8; nb++) {
                uint32_t vh[4], vl[4];
                uint32_t va = vAddr0 + nb * 32;
                ldsm4t(vh, va);
                ldsm4t(vl, va + ATILE);
                mma16816(acc[nb * 2],     aPh[kb2], &vh[0]);
                mma16816(acc[nb * 2],     aPh[kb2], &vl[0]);
                mma16816(acc[nb * 2],     aPl[kb2], &vh[0]);
                mma16816(acc[nb * 2 + 1], aPh[kb2], &vh[2]);
                mma16816(acc[nb * 2 + 1], aPh[kb2], &vl[2]);
                mma16816(acc[nb * 2 + 1], aPl[kb2], &vh[2]);
            }
        }

        __syncthreads();
        if (kt + 2 < nkt) {
            size_t bn = (size_t)(b * Tseq + (kt + 2) * 64) * HD;
            attn_load_stage(sb + AST_OFF + (kt & 1) * ASTAGE,
                            Khi + bn, Klo + bn, Vhi + bn, Vlo + bn, tid);
        }
    }

    __syncthreads();   // Ls atomics + last compute done

    // ---- cross-warp (wn) reduction via smem, normalize, write AO ----
    float* red = (float*)(sm + AST_OFF);   // reuse stage0 (32KB needed)
    int rloc = wm * 16 + (lane >> 2);
    if (wn == 1) {
#pragma unroll
        for (int nn = 0; nn < 16; nn++) {
            int col = nn * 8 + 2 * (lane & 3);
            red[rloc * 128 + col] = acc[nn][0];
            red[rloc * 128 + col + 1] = acc[nn][1];
            red[(rloc + 8) * 128 + col] = acc[nn][2];
            red[(rloc + 8) * 128 + col + 1] = acc[nn][3];
        }
    }
    __syncthreads();
    if (wn == 0) {
        float inv0 = 1.f / Ls[rloc];
        float inv1 = 1.f / Ls[rloc + 8];
        size_t r0g = ((size_t)(b * Tseq + q0 + rloc)) * Dm + h * HD;
        size_t r1g = r0g + 8 * (size_t)Dm;
#pragma unroll
        for (int nn = 0; nn < 16; nn++) {
            int col = nn * 8 + 2 * (lane & 3);
            float o0 = (acc[nn][0] + red[rloc * 128 + col]) * inv0;
            float o1 = (acc[nn][1] + red[rloc * 128 + col + 1]) * inv0;
            float o2 = (acc[nn][2] + red[(rloc + 8) * 128 + col]) * inv1;
            float o3 = (acc[nn][3] + red[(rloc + 8) * 128 + col + 1]) * inv1;
            uint32_t h01, l01, h23, l23;
            split_pack2(o0, o1, h01, l01);
            split_pack2(o2, o3, h23, l23);
            *(uint32_t*)(AOhi + r0g + col) = h01;
            *(uint32_t*)(AOlo + r0g + col) = l01;
            *(uint32_t*)(AOhi + r1g + col) = h23;
            *(uint32_t*)(AOlo + r1g + col) = l23;
        }
    }
}

// ---------------------------------------------------------------------------
extern "C" void kernel_launch(void* const* d_in, const int* in_sizes, int n_in,
                              void* d_out, int out_size)
{
    const float* x    = (const float*)d_in[0];
    const float* Wq   = (const float*)d_in[1];
    const float* Wk   = (const float*)d_in[2];
    const float* Wv   = (const float*)d_in[3];
    const float* Wo   = (const float*)d_in[4];
    const float* gain = (const float*)d_in[5];
    const float* cosb = (const float*)d_in[6];
    const float* sinb = (const float*)d_in[7];
    float* out = (float*)d_out;

    __nv_bfloat16 *xhi, *xlo, *Whi, *Wlo, *Qhi, *Qlo, *Khi, *Klo, *Vhi, *Vlo, *AOhi, *AOlo;
    float *QKV;
    cudaGetSymbolAddress((void**)&xhi, g_xhi);
    cudaGetSymbolAddress((void**)&xlo, g_xlo);
    cudaGetSymbolAddress((void**)&Whi, g_Whi);
    cudaGetSymbolAddress((void**)&Wlo, g_Wlo);
    cudaGetSymbolAddress((void**)&QKV, g_QKV);
    cudaGetSymbolAddress((void**)&Qhi, g_Qhi);
    cudaGetSymbolAddress((void**)&Qlo, g_Qlo);
    cudaGetSymbolAddress((void**)&Khi, g_Khi);
    cudaGetSymbolAddress((void**)&Klo, g_Klo);
    cudaGetSymbolAddress((void**)&Vhi, g_Vhi);
    cudaGetSymbolAddress((void**)&Vlo, g_Vlo);
    cudaGetSymbolAddress((void**)&AOhi, g_AOhi);
    cudaGetSymbolAddress((void**)&AOlo, g_AOlo);

    const int nx = MTOT * Dm;

    split_kernel<<<nx / 4 / 256, 256>>>(x, xhi, xlo, nx);
    split_kernel<<<(1024 * Dm) / 4 / 256, 256>>>(Wq, Whi, Wlo, 1024 * Dm);
    split_kernel<<<(128 * Dm) / 4 / 256, 256>>>(Wk, Whi + (size_t)1024 * Dm, Wlo + (size_t)1024 * Dm, 128 * Dm);
    split_kernel<<<(128 * Dm) / 4 / 256, 256>>>(Wv, Whi + (size_t)1152 * Dm, Wlo + (size_t)1152 * Dm, 128 * Dm);
    split_kernel<<<(1024 * Dm) / 4 / 256, 256>>>(Wo, Whi + (size_t)1280 * Dm, Wlo + (size_t)1280 * Dm, 1024 * Dm);

    cudaFuncSetAttribute(gemm_hmma_kernel, cudaFuncAttributeMaxDynamicSharedMemorySize, GEMM_SMEM);

    // fused QKV projection
    gemm_hmma_kernel<<<dim3(NQKV / 128, MTOT / 128), 256, GEMM_SMEM>>>(
        xhi, xlo, Whi, Wlo, QKV, NQKV);

    // RoPE + split to bf16
    rope_q_split<<<(Bx * Tseq * NH * 64) / 256, 256>>>(QKV, cosb, sinb, gain, Qhi, Qlo);
    rope_k_split<<<(Bx * Tseq * 64) / 256, 256>>>(QKV, cosb, sinb, Khi, Klo);
    v_split<<<(Bx * Tseq * HD) / 256, 256>>>(QKV, Vhi, Vlo);

    // Attention (HMMA)
    cudaFuncSetAttribute(attn_hmma_kernel, cudaFuncAttributeMaxDynamicSharedMemorySize, ATTN_SMEM);
    attn_hmma_kernel<<<dim3(Tseq / 64, NH, Bx), 256, ATTN_SMEM>>>(
        Qhi, Qlo, Khi, Klo, Vhi, Vlo, AOhi, AOlo);

    // Output projection
    gemm_hmma_kernel<<<dim3(Dm / 128, MTOT / 128), 256, GEMM_SMEM>>>(
        AOhi, AOlo, Whi + (size_t)1280 * Dm, Wlo + (size_t)1280 * Dm, out, Dm);
}

// round 7
// speedup vs baseline: 3.1064x; 1.2490x over previous
#include <cuda_runtime.h>
#include <cuda_bf16.h>
#include <math.h>
#include <cstdint>

// Problem constants
#define Bx 4
#define Tseq 2048
#define Dm 1024
#define NH 8
#define HD 128
#define SOFTCAP 30.0f
#define MTOT (Bx * Tseq)          // 8192
#define NQKV 1280                 // 1024 Q + 128 K + 128 V fused
#define NWROWS 2304               // 1280 + 1024 (Wo)

// ---------------------------------------------------------------------------
// Scratch (device globals; no allocation allowed)
// ---------------------------------------------------------------------------
__device__ __nv_bfloat16 g_xhi[(size_t)MTOT * Dm];
__device__ __nv_bfloat16 g_xlo[(size_t)MTOT * Dm];
__device__ __nv_bfloat16 g_Whi[(size_t)NWROWS * Dm];
__device__ __nv_bfloat16 g_Wlo[(size_t)NWROWS * Dm];
__device__ float g_QKV[(size_t)MTOT * NQKV];   // 40MB GEMM output
__device__ __nv_bfloat16 g_Qhi[(size_t)MTOT * Dm];
__device__ __nv_bfloat16 g_Qlo[(size_t)MTOT * Dm];
__device__ __nv_bfloat16 g_Khi[(size_t)MTOT * HD];
__device__ __nv_bfloat16 g_Klo[(size_t)MTOT * HD];
__device__ __nv_bfloat16 g_Vhi[(size_t)MTOT * HD];
__device__ __nv_bfloat16 g_Vlo[(size_t)MTOT * HD];
__device__ __nv_bfloat16 g_AOhi[(size_t)MTOT * Dm];
__device__ __nv_bfloat16 g_AOlo[(size_t)MTOT * Dm];

// ---------------------------------------------------------------------------
// helpers
// ---------------------------------------------------------------------------
__device__ __forceinline__ uint32_t smem_u32(const void* p) {
    uint32_t a;
    asm("{ .reg .u64 t; cvta.to.shared.u64 t, %1; cvt.u32.u64 %0, t; }" : "=r"(a) : "l"(p));
    return a;
}
__device__ __forceinline__ void cpa16(uint32_t s, const void* g) {
    asm volatile("cp.async.cg.shared.global [%0], [%1], 16;" :: "r"(s), "l"(g));
}
__device__ __forceinline__ void ldsm4(uint32_t* r, uint32_t a) {
    asm volatile("ldmatrix.sync.aligned.m8n8.x4.shared.b16 {%0,%1,%2,%3}, [%4];"
        : "=r"(r[0]), "=r"(r[1]), "=r"(r[2]), "=r"(r[3]) : "r"(a));
}
__device__ __forceinline__ void ldsm4t(uint32_t* r, uint32_t a) {
    asm volatile("ldmatrix.sync.aligned.m8n8.x4.trans.shared.b16 {%0,%1,%2,%3}, [%4];"
        : "=r"(r[0]), "=r"(r[1]), "=r"(r[2]), "=r"(r[3]) : "r"(a));
}
__device__ __forceinline__ void mma16816(float* d, const uint32_t* a, const uint32_t* b) {
    asm volatile("mma.sync.aligned.m16n8k16.row.col.f32.bf16.bf16.f32 "
        "{%0,%1,%2,%3}, {%4,%5,%6,%7}, {%8,%9}, {%0,%1,%2,%3};"
        : "+f"(d[0]), "+f"(d[1]), "+f"(d[2]), "+f"(d[3])
        : "r"(a[0]), "r"(a[1]), "r"(a[2]), "r"(a[3]), "r"(b[0]), "r"(b[1]));
}
// split two floats into packed (hi, lo) bf16x2 registers
__device__ __forceinline__ void split_pack2(float x, float y, uint32_t& hi, uint32_t& lo) {
    __nv_bfloat16 xh = __float2bfloat16(x), yh = __float2bfloat16(y);
    float xr = x - __bfloat162float(xh), yr = y - __bfloat162float(yh);
    __nv_bfloat16 xl = __float2bfloat16(xr), yl = __float2bfloat16(yr);
    hi = (uint32_t)(*(uint16_t*)&xh) | ((uint32_t)(*(uint16_t*)&yh) << 16);
    lo = (uint32_t)(*(uint16_t*)&xl) | ((uint32_t)(*(uint16_t*)&yl) << 16);
}

// ---------------------------------------------------------------------------
// split fp32 -> (hi, lo) bf16
// ---------------------------------------------------------------------------
__global__ void split_kernel(const float* __restrict__ src,
                             __nv_bfloat16* __restrict__ hi,
                             __nv_bfloat16* __restrict__ lo, int n)
{
    int i = (blockIdx.x * blockDim.x + threadIdx.x) * 4;
    if (i >= n) return;
    float4 v = *(const float4*)&src[i];
    __nv_bfloat16 h[4], l[4];
    float vv[4] = {v.x, v.y, v.z, v.w};
#pragma unroll
    for (int j = 0; j < 4; j++) {
        h[j] = __float2bfloat16(vv[j]);
        l[j] = __float2bfloat16(vv[j] - __bfloat162float(h[j]));
    }
    *(uint2*)&hi[i] = *(uint2*)h;
    *(uint2*)&lo[i] = *(uint2*)l;
}

// ---------------------------------------------------------------------------
// HMMA GEMM: C tile = A[128,1024] @ B[128,1024]^T, split bf16.
// 2 CTAs/SM target: B frags loaded per-nf2 to keep regs <= 128.
// ---------------------------------------------------------------------------
#define GBK 32
#define NCHUNK (Dm / GBK)          // 32
#define ASTRIDE 80
#define TILE_B (128 * ASTRIDE)
#define STAGE_B (4 * TILE_B)
#define GEMM_SMEM (2 * STAGE_B)

__device__ __forceinline__ void gemm_load_chunk(
    uint32_t sbase, const __nv_bfloat16* gAh, const __nv_bfloat16* gAl,
    const __nv_bfloat16* gBh, const __nv_bfloat16* gBl, int tid, int c)
{
    uint32_t st = sbase + (c & 1) * STAGE_B;
    int k0 = c * GBK;
    const __nv_bfloat16* gp[4] = {gAh, gAl, gBh, gBl};
#pragma unroll
    for (int t = 0; t < 4; t++) {
#pragma unroll
        for (int i = 0; i < 2; i++) {
            int j = tid + i * 256;
            int row = j >> 2, cc = j & 3;
            cpa16(st + t * TILE_B + row * ASTRIDE + cc * 16,
                  gp[t] + (size_t)row * Dm + k0 + cc * 8);
        }
    }
    asm volatile("cp.async.commit_group;" ::: "memory");
}

__global__ __launch_bounds__(256, 2)
void gemm_hmma_kernel(const __nv_bfloat16* __restrict__ Ahi,
                      const __nv_bfloat16* __restrict__ Alo,
                      const __nv_bfloat16* __restrict__ Bhi,
                      const __nv_bfloat16* __restrict__ Blo,
                      float* __restrict__ C, int ldc)
{
    extern __shared__ char smem[];
    uint32_t sbase = smem_u32(smem);
    int tid = threadIdx.x, lane = tid & 31, wid = tid >> 5;
    int wm = wid & 3, wn = wid >> 2;
    int n0 = blockIdx.x * 128, m0 = blockIdx.y * 128;

    const __nv_bfloat16* gAh = Ahi + (size_t)m0 * Dm;
    const __nv_bfloat16* gAl = Alo + (size_t)m0 * Dm;
    const __nv_bfloat16* gBh = Bhi + (size_t)n0 * Dm;
    const __nv_bfloat16* gBl = Blo + (size_t)n0 * Dm;

    float acc[16][4];
#pragma unroll
    for (int f = 0; f < 16; f++)
#pragma unroll
        for (int j = 0; j < 4; j++) acc[f][j] = 0.f;

    gemm_load_chunk(sbase, gAh, gAl, gBh, gBl, tid, 0);
    gemm_load_chunk(sbase, gAh, gAl, gBh, gBl, tid, 1);

    uint32_t a_off = (wm * 32 + (lane & 15)) * ASTRIDE + (lane >> 4) * 16;
    uint32_t b_off = (wn * 64 + (lane & 7) + ((lane >> 4) << 3)) * ASTRIDE
                   + ((lane >> 3) & 1) * 16;

    for (int c = 0; c < NCHUNK; c++) {
        if (c + 1 < NCHUNK)
            asm volatile("cp.async.wait_group 1;" ::: "memory");
        else
            asm volatile("cp.async.wait_group 0;" ::: "memory");
        __syncthreads();

        uint32_t st = sbase + (c & 1) * STAGE_B;
#pragma unroll
        for (int ks = 0; ks < 2; ks++) {
            uint32_t ah[2][4], al[2][4];
#pragma unroll
            for (int mi = 0; mi < 2; mi++) {
                uint32_t addr = st + a_off + mi * 16 * ASTRIDE + ks * 32;
                ldsm4(ah[mi], addr);
                ldsm4(al[mi], addr + TILE_B);
            }
#pragma unroll
            for (int nf2 = 0; nf2 < 4; nf2++) {
                uint32_t addr = st + 2 * TILE_B + b_off + nf2 * 16 * ASTRIDE + ks * 32;
                uint32_t rh[4], rl[4];
                ldsm4(rh, addr);
                ldsm4(rl, addr + TILE_B);
#pragma unroll
                for (int mi = 0; mi < 2; mi++) {
                    float* d0 = acc[mi * 8 + 2 * nf2];
                    float* d1 = acc[mi * 8 + 2 * nf2 + 1];
                    mma16816(d0, ah[mi], &rh[0]);
                    mma16816(d0, ah[mi], &rl[0]);
                    mma16816(d0, al[mi], &rh[0]);
                    mma16816(d1, ah[mi], &rh[2]);
                    mma16816(d1, ah[mi], &rl[2]);
                    mma16816(d1, al[mi], &rh[2]);
                }
            }
        }
        __syncthreads();
        if (c + 2 < NCHUNK)
            gemm_load_chunk(sbase, gAh, gAl, gBh, gBl, tid, c + 2);
    }

#pragma unroll
    for (int mi = 0; mi < 2; mi++)
#pragma unroll
        for (int nf = 0; nf < 8; nf++) {
            float* d = acc[mi * 8 + nf];
            size_t row = (size_t)(m0 + wm * 32 + mi * 16 + (lane >> 2));
            float* cp = C + row * ldc + n0 + wn * 64 + nf * 8 + (lane & 3) * 2;
            *(float2*)cp = make_float2(d[0], d[1]);
            *(float2*)(cp + 8 * (size_t)ldc) = make_float2(d[2], d[3]);
        }
}

// ---------------------------------------------------------------------------
// RoPE + split to bf16(hi,lo). Reads fused QKV fp32.
// ---------------------------------------------------------------------------
__global__ void rope_q_split(const float* __restrict__ QKV,
                             const float* __restrict__ cosb,
                             const float* __restrict__ sinb,
                             const float* __restrict__ gain,
                             __nv_bfloat16* __restrict__ Qhi,
                             __nv_bfloat16* __restrict__ Qlo)
{
    int idx = blockIdx.x * blockDim.x + threadIdx.x;   // B*T*NH*64
    if (idx >= Bx * Tseq * NH * 64) return;
    int d = idx & 63;
    int h = (idx >> 6) & (NH - 1);
    int bt = idx >> 9;
    int t = bt & (Tseq - 1);
    size_t src = (size_t)bt * NQKV + h * HD + d;
    float x1 = QKV[src], x2 = QKV[src + 64];
    float c = cosb[t * 64 + d], s = sinb[t * 64 + d];
    float g = gain[h];
    float y1 = (x1 * c - x2 * s) * g;
    float y2 = (x1 * s + x2 * c) * g;
    size_t o = (size_t)bt * Dm + h * HD + d;
    __nv_bfloat16 h1 = __float2bfloat16(y1), h2 = __float2bfloat16(y2);
    Qhi[o] = h1; Qhi[o + 64] = h2;
    Qlo[o] = __float2bfloat16(y1 - __bfloat162float(h1));
    Qlo[o + 64] = __float2bfloat16(y2 - __bfloat162float(h2));
}

__global__ void rope_k_split(const float* __restrict__ QKV,
                             const float* __restrict__ cosb,
                             const float* __restrict__ sinb,
                             __nv_bfloat16* __restrict__ Khi,
                             __nv_bfloat16* __restrict__ Klo)
{
    int idx = blockIdx.x * blockDim.x + threadIdx.x;   // B*T*64
    if (idx >= Bx * Tseq * 64) return;
    int d = idx & 63;
    int bt = idx >> 6;
    int t = bt & (Tseq - 1);
    size_t src = (size_t)bt * NQKV + 1024 + d;
    float x1 = QKV[src], x2 = QKV[src + 64];
    float c = cosb[t * 64 + d], s = sinb[t * 64 + d];
    float y1 = x1 * c - x2 * s;
    float y2 = x1 * s + x2 * c;
    size_t o = (size_t)bt * HD + d;
    __nv_bfloat16 h1 = __float2bfloat16(y1), h2 = __float2bfloat16(y2);
    Khi[o] = h1; Khi[o + 64] = h2;
    Klo[o] = __float2bfloat16(y1 - __bfloat162float(h1));
    Klo[o + 64] = __float2bfloat16(y2 - __bfloat162float(h2));
}

__global__ void v_split(const float* __restrict__ QKV,
                        __nv_bfloat16* __restrict__ Vhi,
                        __nv_bfloat16* __restrict__ Vlo)
{
    int idx = blockIdx.x * blockDim.x + threadIdx.x;   // B*T*128
    if (idx >= Bx * Tseq * HD) return;
    int d = idx & 127;
    int bt = idx >> 7;
    float v = QKV[(size_t)bt * NQKV + 1152 + d];
    __nv_bfloat16 h = __float2bfloat16(v);
    Vhi[idx] = h;
    Vlo[idx] = __float2bfloat16(v - __bfloat162float(h));
}

// ---------------------------------------------------------------------------
// HMMA flash attention, split bf16 (Q,K,P,V all hi+lo, 3-term MMAs).
// Block: (q-tile 64, head, batch), 256 threads = 8 warps (4m x 2n).
// ---------------------------------------------------------------------------
#define KSTR 272
#define ATILE 17408                 // 64 * KSTR
#define ASTAGE (4 * ATILE)          // Khi|Klo|Vhi|Vlo
#define AQ_OFF 0
#define AST_OFF (2 * ATILE)         // 34816
#define ALS_OFF (AST_OFF + 2 * ASTAGE)   // 174080
#define ATTN_SMEM (ALS_OFF + 256)

__device__ __forceinline__ void attn_load_stage(uint32_t st,
    const __nv_bfloat16* kh, const __nv_bfloat16* kl,
    const __nv_bfloat16* vh, const __nv_bfloat16* vl, int tid)
{
#pragma unroll
    for (int i = 0; i < 4; i++) {
        int j = tid + i * 256;
        int row = j >> 4, c = j & 15;
        uint32_t so = row * KSTR + c * 16;
        size_t go = (size_t)row * HD + c * 8;
        cpa16(st + so, kh + go);
        cpa16(st + ATILE + so, kl + go);
        cpa16(st + 2 * ATILE + so, vh + go);
        cpa16(st + 3 * ATILE + so, vl + go);
    }
    asm volatile("cp.async.commit_group;" ::: "memory");
}

__global__ __launch_bounds__(256, 1)
void attn_hmma_kernel(const __nv_bfloat16* __restrict__ Qhi,
                      const __nv_bfloat16* __restrict__ Qlo,
                      const __nv_bfloat16* __restrict__ Khi,
                      const __nv_bfloat16* __restrict__ Klo,
                      const __nv_bfloat16* __restrict__ Vhi,
                      const __nv_bfloat16* __restrict__ Vlo,
                      __nv_bfloat16* __restrict__ AOhi,
                      __nv_bfloat16* __restrict__ AOlo)
{
    extern __shared__ char sm[];
    uint32_t sb = smem_u32(sm);
    float* Ls = (float*)(sm + ALS_OFF);

    int qt = gridDim.x - 1 - blockIdx.x;     // long blocks first
    int h = blockIdx.y, b = blockIdx.z;
    int q0 = qt * 64;
    int tid = threadIdx.x, lane = tid & 31, wid = tid >> 5;
    int wm = wid & 3, wn = wid >> 2;
    int nkt = qt + 1;

    if (tid < 64) Ls[tid] = 0.f;

    // Q tile (hi,lo) via cp.async
    {
        const __nv_bfloat16* qh = Qhi + ((size_t)(b * Tseq + q0)) * Dm + h * HD;
        const __nv_bfloat16* ql = Qlo + ((size_t)(b * Tseq + q0)) * Dm + h * HD;
#pragma unroll
        for (int i = 0; i < 4; i++) {
            int j = tid + i * 256;
            int row = j >> 4, c = j & 15;
            uint32_t so = row * KSTR + c * 16;
            size_t go = (size_t)row * Dm + c * 8;
            cpa16(sb + AQ_OFF + so, qh + go);
            cpa16(sb + AQ_OFF + ATILE + so, ql + go);
        }
        asm volatile("cp.async.commit_group;" ::: "memory");
    }
    {
        size_t base = (size_t)(b * Tseq) * HD;
        attn_load_stage(sb + AST_OFF, Khi + base, Klo + base, Vhi + base, Vlo + base, tid);
        if (nkt > 1) {
            size_t b1 = base + 64 * HD;
            attn_load_stage(sb + AST_OFF + ASTAGE, Khi + b1, Klo + b1, Vhi + b1, Vlo + b1, tid);
        }
    }

    float acc[16][4];
#pragma unroll
    for (int f = 0; f < 16; f++)
#pragma unroll
        for (int j = 0; j < 4; j++) acc[f][j] = 0.f;

    const float cap2 = 2.0f * 0.0029462782549439483f;   // 2/(sqrt(128)*30)
    const float E30 = 1.0686474581524463e13f;           // exp(30)

    uint32_t aQoff = AQ_OFF + (wm * 16 + (lane & 15)) * KSTR + (lane >> 4) * 16;
    uint32_t bKrow = wn * 32 + (lane & 7) + ((lane >> 4) & 1) * 8;
    uint32_t bKoff = bKrow * KSTR + ((lane >> 3) & 1) * 16;

    for (int kt = 0; kt < nkt; kt++) {
        if (kt + 1 < nkt)
            asm volatile("cp.async.wait_group 1;" ::: "memory");
        else
            asm volatile("cp.async.wait_group 0;" ::: "memory");
        __syncthreads();

        uint32_t stK = sb + AST_OFF + (kt & 1) * ASTAGE;
        uint32_t stV = stK + 2 * ATILE;

        // ---- S = Q K^T (warp tile 16 x 32), 3-term split ----
        float sfrag[4][4];
#pragma unroll
        for (int f = 0; f < 4; f++)
#pragma unroll
            for (int e = 0; e < 4; e++) sfrag[f][e] = 0.f;

#pragma unroll
        for (int kb = 0; kb < 8; kb++) {
            uint32_t ah[4], al[4];
            ldsm4(ah, sb + aQoff + kb * 32);
            ldsm4(al, sb + aQoff + ATILE + kb * 32);
#pragma unroll
            for (int nb = 0; nb < 2; nb++) {
                uint32_t bhh[4], bll[4];
                uint32_t baddr = stK + bKoff + nb * 16 * KSTR + kb * 32;
                ldsm4(bhh, baddr);
                ldsm4(bll, baddr + ATILE);
                mma16816(sfrag[nb * 2],     ah, &bhh[0]);
                mma16816(sfrag[nb * 2],     ah, &bll[0]);
                mma16816(sfrag[nb * 2],     al, &bhh[0]);
                mma16816(sfrag[nb * 2 + 1], ah, &bhh[2]);
                mma16816(sfrag[nb * 2 + 1], ah, &bll[2]);
                mma16816(sfrag[nb * 2 + 1], al, &bhh[2]);
            }
        }

        // ---- softcap + causal mask + exp, rowsum ----
        // p = exp(30*tanh(s*scale/30)) = E30 * exp(-60/(exp(2*s*scale/30)+1))
        bool diag = (kt == nkt - 1);
        int rloc = wm * 16 + (lane >> 2);
        float rs0 = 0.f, rs1 = 0.f;
        float p[4][4];
#pragma unroll
        for (int nf = 0; nf < 4; nf++) {
            int colb = wn * 32 + nf * 8 + 2 * (lane & 3);
#pragma unroll
            for (int e = 0; e < 4; e++) {
                int row = rloc + ((e >> 1) << 3);
                int col = colb + (e & 1);
                float ex = __expf(sfrag[nf][e] * cap2);
                float pv = E30 * __expf(-__fdividef(60.f, ex + 1.f));
                if (diag && col > row) pv = 0.f;
                p[nf][e] = pv;
                if (e < 2) rs0 += pv; else rs1 += pv;
            }
        }
        rs0 += __shfl_xor_sync(0xffffffffu, rs0, 1);
        rs0 += __shfl_xor_sync(0xffffffffu, rs0, 2);
        rs1 += __shfl_xor_sync(0xffffffffu, rs1, 1);
        rs1 += __shfl_xor_sync(0xffffffffu, rs1, 2);
        if ((lane & 3) == 0) {
            atomicAdd(&Ls[rloc], rs0);
            atomicAdd(&Ls[rloc + 8], rs1);
        }

        // ---- P -> A frags (split) ----
        uint32_t aPh[2][4], aPl[2][4];
#pragma unroll
        for (int kb2 = 0; kb2 < 2; kb2++) {
            int j = kb2 * 2;
            split_pack2(p[j][0],     p[j][1],     aPh[kb2][0], aPl[kb2][0]);
            split_pack2(p[j][2],     p[j][3],     aPh[kb2][1], aPl[kb2][1]);
            split_pack2(p[j + 1][0], p[j + 1][1], aPh[kb2][2], aPl[kb2][2]);
            split_pack2(p[j + 1][2], p[j + 1][3], aPh[kb2][3], aPl[kb2][3]);
        }

        // ---- acc += P @ V (k-slice = warp's 32 cols) ----
#pragma unroll
        for (int kb2 = 0; kb2 < 2; kb2++) {
            int t0 = wn * 32 + kb2 * 16;
            uint32_t vAddr0 = stV + (t0 + (lane & 15)) * KSTR + (lane >> 4) * 16;
#pragma unroll
            for (int nb = 0; nb < 8; nb++) {
                uint32_t vh[4], vl[4];
                uint32_t va = vAddr0 + nb * 32;
                ldsm4t(vh, va);
                ldsm4t(vl, va + ATILE);
                mma16816(acc[nb * 2],     aPh[kb2], &vh[0]);
                mma16816(acc[nb * 2],     aPh[kb2], &vl[0]);
                mma16816(acc[nb * 2],     aPl[kb2], &vh[0]);
                mma16816(acc[nb * 2 + 1], aPh[kb2], &vh[2]);
                mma16816(acc[nb * 2 + 1], aPh[kb2], &vl[2]);
                mma16816(acc[nb * 2 + 1], aPl[kb2], &vh[2]);
            }
        }

        __syncthreads();
        if (kt + 2 < nkt) {
            size_t bn = (size_t)(b * Tseq + (kt + 2) * 64) * HD;
            attn_load_stage(sb + AST_OFF + (kt & 1) * ASTAGE,
                            Khi + bn, Klo + bn, Vhi + bn, Vlo + bn, tid);
        }
    }

    __syncthreads();

    // ---- cross-warp (wn) reduction via smem, normalize, write AO ----
    float* red = (float*)(sm + AST_OFF);
    int rloc = wm * 16 + (lane >> 2);
    if (wn == 1) {
#pragma unroll
        for (int nn = 0; nn < 16; nn++) {
            int col = nn * 8 + 2 * (lane & 3);
            red[rloc * 128 + col] = acc[nn][0];
            red[rloc * 128 + col + 1] = acc[nn][1];
            red[(rloc + 8) * 128 + col] = acc[nn][2];
            red[(rloc + 8) * 128 + col + 1] = acc[nn][3];
        }
    }
    __syncthreads();
    if (wn == 0) {
        float inv0 = __fdividef(1.f, Ls[rloc]);
        float inv1 = __fdividef(1.f, Ls[rloc + 8]);
        size_t r0g = ((size_t)(b * Tseq + q0 + rloc)) * Dm + h * HD;
        size_t r1g = r0g + 8 * (size_t)Dm;
#pragma unroll
        for (int nn = 0; nn < 16; nn++) {
            int col = nn * 8 + 2 * (lane & 3);
            float o0 = (acc[nn][0] + red[rloc * 128 + col]) * inv0;
            float o1 = (acc[nn][1] + red[rloc * 128 + col + 1]) * inv0;
            float o2 = (acc[nn][2] + red[(rloc + 8) * 128 + col]) * inv1;
            float o3 = (acc[nn][3] + red[(rloc + 8) * 128 + col + 1]) * inv1;
            uint32_t h01, l01, h23, l23;
            split_pack2(o0, o1, h01, l01);
            split_pack2(o2, o3, h23, l23);
            *(uint32_t*)(AOhi + r0g + col) = h01;
            *(uint32_t*)(AOlo + r0g + col) = l01;
            *(uint32_t*)(AOhi + r1g + col) = h23;
            *(uint32_t*)(AOlo + r1g + col) = l23;
        }
    }
}

// ---------------------------------------------------------------------------
extern "C" void kernel_launch(void* const* d_in, const int* in_sizes, int n_in,
                              void* d_out, int out_size)
{
    const float* x    = (const float*)d_in[0];
    const float* Wq   = (const float*)d_in[1];
    const float* Wk   = (const float*)d_in[2];
    const float* Wv   = (const float*)d_in[3];
    const float* Wo   = (const float*)d_in[4];
    const float* gain = (const float*)d_in[5];
    const float* cosb = (const float*)d_in[6];
    const float* sinb = (const float*)d_in[7];
    float* out = (float*)d_out;

    __nv_bfloat16 *xhi, *xlo, *Whi, *Wlo, *Qhi, *Qlo, *Khi, *Klo, *Vhi, *Vlo, *AOhi, *AOlo;
    float *QKV;
    cudaGetSymbolAddress((void**)&xhi, g_xhi);
    cudaGetSymbolAddress((void**)&xlo, g_xlo);
    cudaGetSymbolAddress((void**)&Whi, g_Whi);
    cudaGetSymbolAddress((void**)&Wlo, g_Wlo);
    cudaGetSymbolAddress((void**)&QKV, g_QKV);
    cudaGetSymbolAddress((void**)&Qhi, g_Qhi);
    cudaGetSymbolAddress((void**)&Qlo, g_Qlo);
    cudaGetSymbolAddress((void**)&Khi, g_Khi);
    cudaGetSymbolAddress((void**)&Klo, g_Klo);
    cudaGetSymbolAddress((void**)&Vhi, g_Vhi);
    cudaGetSymbolAddress((void**)&Vlo, g_Vlo);
    cudaGetSymbolAddress((void**)&AOhi, g_AOhi);
    cudaGetSymbolAddress((void**)&AOlo, g_AOlo);

    const int nx = MTOT * Dm;

    split_kernel<<<nx / 4 / 256, 256>>>(x, xhi, xlo, nx);
    split_kernel<<<(1024 * Dm) / 4 / 256, 256>>>(Wq, Whi, Wlo, 1024 * Dm);
    split_kernel<<<(128 * Dm) / 4 / 256, 256>>>(Wk, Whi + (size_t)1024 * Dm, Wlo + (size_t)1024 * Dm, 128 * Dm);
    split_kernel<<<(128 * Dm) / 4 / 256, 256>>>(Wv, Whi + (size_t)1152 * Dm, Wlo + (size_t)1152 * Dm, 128 * Dm);
    split_kernel<<<(1024 * Dm) / 4 / 256, 256>>>(Wo, Whi + (size_t)1280 * Dm, Wlo + (size_t)1280 * Dm, 1024 * Dm);

    cudaFuncSetAttribute(gemm_hmma_kernel, cudaFuncAttributeMaxDynamicSharedMemorySize, GEMM_SMEM);

    // fused QKV projection
    gemm_hmma_kernel<<<dim3(NQKV / 128, MTOT / 128), 256, GEMM_SMEM>>>(
        xhi, xlo, Whi, Wlo, QKV, NQKV);

    // RoPE + split to bf16
    rope_q_split<<<(Bx * Tseq * NH * 64) / 256, 256>>>(QKV, cosb, sinb, gain, Qhi, Qlo);
    rope_k_split<<<(Bx * Tseq * 64) / 256, 256>>>(QKV, cosb, sinb, Khi, Klo);
    v_split<<<(Bx * Tseq * HD) / 256, 256>>>(QKV, Vhi, Vlo);

    // Attention (HMMA)
    cudaFuncSetAttribute(attn_hmma_kernel, cudaFuncAttributeMaxDynamicSharedMemorySize, ATTN_SMEM);
    attn_hmma_kernel<<<dim3(Tseq / 64, NH, Bx), 256, ATTN_SMEM>>>(
        Qhi, Qlo, Khi, Klo, Vhi, Vlo, AOhi, AOlo);

    // Output projection
    gemm_hmma_kernel<<<dim3(Dm / 128, MTOT / 128), 256, GEMM_SMEM>>>(
        AOhi, AOlo, Whi + (size_t)1280 * Dm, Wlo + (size_t)1280 * Dm, out, Dm);
}

// round 11
// speedup vs baseline: 3.1068x; 1.0001x over previous
#include <cuda_runtime.h>
#include <cuda_bf16.h>
#include <math.h>
#include <cstdint>

// Problem constants
#define Bx 4
#define Tseq 2048
#define Dm 1024
#define NH 8
#define HD 128
#define SOFTCAP 30.0f
#define MTOT (Bx * Tseq)          // 8192
#define NQKV 1280                 // 1024 Q + 128 K + 128 V fused
#define NWROWS 2304               // 1280 + 1024 (Wo)

// ---------------------------------------------------------------------------
// Scratch (device globals; no allocation allowed)
// ---------------------------------------------------------------------------
__device__ __nv_bfloat16 g_xhi[(size_t)MTOT * Dm];
__device__ __nv_bfloat16 g_xlo[(size_t)MTOT * Dm];
__device__ __nv_bfloat16 g_Whi[(size_t)NWROWS * Dm];
__device__ __nv_bfloat16 g_Wlo[(size_t)NWROWS * Dm];
__device__ float g_QKV[(size_t)MTOT * NQKV];   // 40MB GEMM output
__device__ __nv_bfloat16 g_Qhi[(size_t)MTOT * Dm];
__device__ __nv_bfloat16 g_Qlo[(size_t)MTOT * Dm];
__device__ __nv_bfloat16 g_Khi[(size_t)MTOT * HD];
__device__ __nv_bfloat16 g_Klo[(size_t)MTOT * HD];
__device__ __nv_bfloat16 g_Vhi[(size_t)MTOT * HD];
__device__ __nv_bfloat16 g_Vlo[(size_t)MTOT * HD];
__device__ __nv_bfloat16 g_AOhi[(size_t)MTOT * Dm];
__device__ __nv_bfloat16 g_AOlo[(size_t)MTOT * Dm];

// ---------------------------------------------------------------------------
// helpers
// ---------------------------------------------------------------------------
__device__ __forceinline__ uint32_t smem_u32(const void* p) {
    uint32_t a;
    asm("{ .reg .u64 t; cvta.to.shared.u64 t, %1; cvt.u32.u64 %0, t; }" : "=r"(a) : "l"(p));
    return a;
}
__device__ __forceinline__ void cpa16(uint32_t s, const void* g) {
    asm volatile("cp.async.cg.shared.global [%0], [%1], 16;" :: "r"(s), "l"(g));
}
__device__ __forceinline__ void ldsm4(uint32_t* r, uint32_t a) {
    asm volatile("ldmatrix.sync.aligned.m8n8.x4.shared.b16 {%0,%1,%2,%3}, [%4];"
        : "=r"(r[0]), "=r"(r[1]), "=r"(r[2]), "=r"(r[3]) : "r"(a));
}
__device__ __forceinline__ void ldsm4t(uint32_t* r, uint32_t a) {
    asm volatile("ldmatrix.sync.aligned.m8n8.x4.trans.shared.b16 {%0,%1,%2,%3}, [%4];"
        : "=r"(r[0]), "=r"(r[1]), "=r"(r[2]), "=r"(r[3]) : "r"(a));
}
__device__ __forceinline__ void mma16816(float* d, const uint32_t* a, const uint32_t* b) {
    asm volatile("mma.sync.aligned.m16n8k16.row.col.f32.bf16.bf16.f32 "
        "{%0,%1,%2,%3}, {%4,%5,%6,%7}, {%8,%9}, {%0,%1,%2,%3};"
        : "+f"(d[0]), "+f"(d[1]), "+f"(d[2]), "+f"(d[3])
        : "r"(a[0]), "r"(a[1]), "r"(a[2]), "r"(a[3]), "r"(b[0]), "r"(b[1]));
}
// split two floats into packed (hi, lo) bf16x2 registers
__device__ __forceinline__ void split_pack2(float x, float y, uint32_t& hi, uint32_t& lo) {
    __nv_bfloat16 xh = __float2bfloat16(x), yh = __float2bfloat16(y);
    float xr = x - __bfloat162float(xh), yr = y - __bfloat162float(yh);
    __nv_bfloat16 xl = __float2bfloat16(xr), yl = __float2bfloat16(yr);
    hi = (uint32_t)(*(uint16_t*)&xh) | ((uint32_t)(*(uint16_t*)&yh) << 16);
    lo = (uint32_t)(*(uint16_t*)&xl) | ((uint32_t)(*(uint16_t*)&yl) << 16);
}

// ---------------------------------------------------------------------------
// split fp32 -> (hi, lo) bf16  (x input)
// ---------------------------------------------------------------------------
__global__ void split_kernel(const float* __restrict__ src,
                             __nv_bfloat16* __restrict__ hi,
                             __nv_bfloat16* __restrict__ lo, int n)
{
    int i = (blockIdx.x * blockDim.x + threadIdx.x) * 4;
    if (i >= n) return;
    float4 v = *(const float4*)&src[i];
    __nv_bfloat16 h[4], l[4];
    float vv[4] = {v.x, v.y, v.z, v.w};
#pragma unroll
    for (int j = 0; j < 4; j++) {
        h[j] = __float2bfloat16(vv[j]);
        l[j] = __float2bfloat16(vv[j] - __bfloat162float(h[j]));
    }
    *(uint2*)&hi[i] = *(uint2*)h;
    *(uint2*)&lo[i] = *(uint2*)l;
}

// fused split of all four weight matrices into the packed W buffer
__global__ void split_w4_kernel(const float* __restrict__ Wq,
                                const float* __restrict__ Wk,
                                const float* __restrict__ Wv,
                                const float* __restrict__ Wo,
                                __nv_bfloat16* __restrict__ hi,
                                __nv_bfloat16* __restrict__ lo)
{
    int i = (blockIdx.x * blockDim.x + threadIdx.x) * 4;   // [0, NWROWS*Dm)
    int row = i >> 10;
    int col = i & 1023;
    const float* src;
    int r;
    if (row < 1024)      { src = Wq; r = row; }
    else if (row < 1152) { src = Wk; r = row - 1024; }
    else if (row < 1280) { src = Wv; r = row - 1152; }
    else                 { src = Wo; r = row - 1280; }
    float4 v = *(const float4*)&src[(size_t)r * Dm + col];
    __nv_bfloat16 h[4], l[4];
    float vv[4] = {v.x, v.y, v.z, v.w};
#pragma unroll
    for (int j = 0; j < 4; j++) {
        h[j] = __float2bfloat16(vv[j]);
        l[j] = __float2bfloat16(vv[j] - __bfloat162float(h[j]));
    }
    *(uint2*)&hi[i] = *(uint2*)h;
    *(uint2*)&lo[i] = *(uint2*)l;
}

// ---------------------------------------------------------------------------
// HMMA GEMM (unchanged from R7): C tile = A[128,1024] @ B[128,1024]^T.
// ---------------------------------------------------------------------------
#define GBK 32
#define NCHUNK (Dm / GBK)          // 32
#define ASTRIDE 80
#define TILE_B (128 * ASTRIDE)
#define STAGE_B (4 * TILE_B)
#define GEMM_SMEM (2 * STAGE_B)

__device__ __forceinline__ void gemm_load_chunk(
    uint32_t sbase, const __nv_bfloat16* gAh, const __nv_bfloat16* gAl,
    const __nv_bfloat16* gBh, const __nv_bfloat16* gBl, int tid, int c)
{
    uint32_t st = sbase + (c & 1) * STAGE_B;
    int k0 = c * GBK;
    const __nv_bfloat16* gp[4] = {gAh, gAl, gBh, gBl};
#pragma unroll
    for (int t = 0; t < 4; t++) {
#pragma unroll
        for (int i = 0; i < 2; i++) {
            int j = tid + i * 256;
            int row = j >> 2, cc = j & 3;
            cpa16(st + t * TILE_B + row * ASTRIDE + cc * 16,
                  gp[t] + (size_t)row * Dm + k0 + cc * 8);
        }
    }
    asm volatile("cp.async.commit_group;" ::: "memory");
}

__global__ __launch_bounds__(256, 2)
void gemm_hmma_kernel(const __nv_bfloat16* __restrict__ Ahi,
                      const __nv_bfloat16* __restrict__ Alo,
                      const __nv_bfloat16* __restrict__ Bhi,
                      const __nv_bfloat16* __restrict__ Blo,
                      float* __restrict__ C, int ldc)
{
    extern __shared__ char smem[];
    uint32_t sbase = smem_u32(smem);
    int tid = threadIdx.x, lane = tid & 31, wid = tid >> 5;
    int wm = wid & 3, wn = wid >> 2;
    int n0 = blockIdx.x * 128, m0 = blockIdx.y * 128;

    const __nv_bfloat16* gAh = Ahi + (size_t)m0 * Dm;
    const __nv_bfloat16* gAl = Alo + (size_t)m0 * Dm;
    const __nv_bfloat16* gBh = Bhi + (size_t)n0 * Dm;
    const __nv_bfloat16* gBl = Blo + (size_t)n0 * Dm;

    float acc[16][4];
#pragma unroll
    for (int f = 0; f < 16; f++)
#pragma unroll
        for (int j = 0; j < 4; j++) acc[f][j] = 0.f;

    gemm_load_chunk(sbase, gAh, gAl, gBh, gBl, tid, 0);
    gemm_load_chunk(sbase, gAh, gAl, gBh, gBl, tid, 1);

    uint32_t a_off = (wm * 32 + (lane & 15)) * ASTRIDE + (lane >> 4) * 16;
    uint32_t b_off = (wn * 64 + (lane & 7) + ((lane >> 4) << 3)) * ASTRIDE
                   + ((lane >> 3) & 1) * 16;

    for (int c = 0; c < NCHUNK; c++) {
        if (c + 1 < NCHUNK)
            asm volatile("cp.async.wait_group 1;" ::: "memory");
        else
            asm volatile("cp.async.wait_group 0;" ::: "memory");
        __syncthreads();

        uint32_t st = sbase + (c & 1) * STAGE_B;
#pragma unroll
        for (int ks = 0; ks < 2; ks++) {
            uint32_t ah[2][4], al[2][4];
#pragma unroll
            for (int mi = 0; mi < 2; mi++) {
                uint32_t addr = st + a_off + mi * 16 * ASTRIDE + ks * 32;
                ldsm4(ah[mi], addr);
                ldsm4(al[mi], addr + TILE_B);
            }
#pragma unroll
            for (int nf2 = 0; nf2 < 4; nf2++) {
                uint32_t addr = st + 2 * TILE_B + b_off + nf2 * 16 * ASTRIDE + ks * 32;
                uint32_t rh[4], rl[4];
                ldsm4(rh, addr);
                ldsm4(rl, addr + TILE_B);
#pragma unroll
                for (int mi = 0; mi < 2; mi++) {
                    float* d0 = acc[mi * 8 + 2 * nf2];
                    float* d1 = acc[mi * 8 + 2 * nf2 + 1];
                    mma16816(d0, ah[mi], &rh[0]);
                    mma16816(d0, ah[mi], &rl[0]);
                    mma16816(d0, al[mi], &rh[0]);
                    mma16816(d1, ah[mi], &rh[2]);
                    mma16816(d1, ah[mi], &rl[2]);
                    mma16816(d1, al[mi], &rh[2]);
                }
            }
        }
        __syncthreads();
        if (c + 2 < NCHUNK)
            gemm_load_chunk(sbase, gAh, gAl, gBh, gBl, tid, c + 2);
    }

#pragma unroll
    for (int mi = 0; mi < 2; mi++)
#pragma unroll
        for (int nf = 0; nf < 8; nf++) {
            float* d = acc[mi * 8 + nf];
            size_t row = (size_t)(m0 + wm * 32 + mi * 16 + (lane >> 2));
            float* cp = C + row * ldc + n0 + wn * 64 + nf * 8 + (lane & 3) * 2;
            *(float2*)cp = make_float2(d[0], d[1]);
            *(float2*)(cp + 8 * (size_t)ldc) = make_float2(d[2], d[3]);
        }
}

// ---------------------------------------------------------------------------
// RoPE + split to bf16(hi,lo). Reads fused QKV fp32.
// ---------------------------------------------------------------------------
__global__ void rope_q_split(const float* __restrict__ QKV,
                             const float* __restrict__ cosb,
                             const float* __restrict__ sinb,
                             const float* __restrict__ gain,
                             __nv_bfloat16* __restrict__ Qhi,
                             __nv_bfloat16* __restrict__ Qlo)
{
    int idx = blockIdx.x * blockDim.x + threadIdx.x;   // B*T*NH*64
    if (idx >= Bx * Tseq * NH * 64) return;
    int d = idx & 63;
    int h = (idx >> 6) & (NH - 1);
    int bt = idx >> 9;
    int t = bt & (Tseq - 1);
    size_t src = (size_t)bt * NQKV + h * HD + d;
    float x1 = QKV[src], x2 = QKV[src + 64];
    float c = cosb[t * 64 + d], s = sinb[t * 64 + d];
    float g = gain[h];
    float y1 = (x1 * c - x2 * s) * g;
    float y2 = (x1 * s + x2 * c) * g;
    size_t o = (size_t)bt * Dm + h * HD + d;
    __nv_bfloat16 h1 = __float2bfloat16(y1), h2 = __float2bfloat16(y2);
    Qhi[o] = h1; Qhi[o + 64] = h2;
    Qlo[o] = __float2bfloat16(y1 - __bfloat162float(h1));
    Qlo[o + 64] = __float2bfloat16(y2 - __bfloat162float(h2));
}

__global__ void rope_k_split(const float* __restrict__ QKV,
                             const float* __restrict__ cosb,
                             const float* __restrict__ sinb,
                             __nv_bfloat16* __restrict__ Khi,
                             __nv_bfloat16* __restrict__ Klo)
{
    int idx = blockIdx.x * blockDim.x + threadIdx.x;   // B*T*64
    if (idx >= Bx * Tseq * 64) return;
    int d = idx & 63;
    int bt = idx >> 6;
    int t = bt & (Tseq - 1);
    size_t src = (size_t)bt * NQKV + 1024 + d;
    float x1 = QKV[src], x2 = QKV[src + 64];
    float c = cosb[t * 64 + d], s = sinb[t * 64 + d];
    float y1 = x1 * c - x2 * s;
    float y2 = x1 * s + x2 * c;
    size_t o = (size_t)bt * HD + d;
    __nv_bfloat16 h1 = __float2bfloat16(y1), h2 = __float2bfloat16(y2);
    Khi[o] = h1; Khi[o + 64] = h2;
    Klo[o] = __float2bfloat16(y1 - __bfloat162float(h1));
    Klo[o + 64] = __float2bfloat16(y2 - __bfloat162float(h2));
}

__global__ void v_split(const float* __restrict__ QKV,
                        __nv_bfloat16* __restrict__ Vhi,
                        __nv_bfloat16* __restrict__ Vlo)
{
    int idx = blockIdx.x * blockDim.x + threadIdx.x;   // B*T*128
    if (idx >= Bx * Tseq * HD) return;
    int d = idx & 127;
    int bt = idx >> 7;
    float v = QKV[(size_t)bt * NQKV + 1152 + d];
    __nv_bfloat16 h = __float2bfloat16(v);
    Vhi[idx] = h;
    Vlo[idx] = __float2bfloat16(v - __bfloat162float(h));
}

// ---------------------------------------------------------------------------
// HMMA flash attention, split bf16. M-tile = 128 q-rows, 512 threads =
// 16 warps (8m x 2n), K-tile = 64, double-buffered cp.async.
// ---------------------------------------------------------------------------
#define KSTR 272
#define KTILE (64 * KSTR)            // 17408
#define QTILE (128 * KSTR)           // 34816
#define ASTAGE (4 * KTILE)           // Khi|Klo|Vhi|Vlo
#define AQ_OFF 0
#define AST_OFF (2 * QTILE)          // 69632
#define ALS_OFF (AST_OFF + 2 * ASTAGE)   // 208896
#define ATTN_SMEM (ALS_OFF + 512)

__device__ __forceinline__ void attn_load_stage(uint32_t st,
    const __nv_bfloat16* kh, const __nv_bfloat16* kl,
    const __nv_bfloat16* vh, const __nv_bfloat16* vl, int tid)
{
#pragma unroll
    for (int i = 0; i < 2; i++) {
        int j = tid + i * 512;
        int row = j >> 4, c = j & 15;
        uint32_t so = row * KSTR + c * 16;
        size_t go = (size_t)row * HD + c * 8;
        cpa16(st + so, kh + go);
        cpa16(st + KTILE + so, kl + go);
        cpa16(st + 2 * KTILE + so, vh + go);
        cpa16(st + 3 * KTILE + so, vl + go);
    }
    asm volatile("cp.async.commit_group;" ::: "memory");
}

__global__ __launch_bounds__(512, 1)
void attn_hmma_kernel(const __nv_bfloat16* __restrict__ Qhi,
                      const __nv_bfloat16* __restrict__ Qlo,
                      const __nv_bfloat16* __restrict__ Khi,
                      const __nv_bfloat16* __restrict__ Klo,
                      const __nv_bfloat16* __restrict__ Vhi,
                      const __nv_bfloat16* __restrict__ Vlo,
                      __nv_bfloat16* __restrict__ AOhi,
                      __nv_bfloat16* __restrict__ AOlo)
{
    extern __shared__ char sm[];
    uint32_t sb = smem_u32(sm);
    float* Ls = (float*)(sm + ALS_OFF);

    int qt = gridDim.x - 1 - blockIdx.x;     // long blocks first
    int h = blockIdx.y, b = blockIdx.z;
    int q0 = qt * 128;
    int tid = threadIdx.x, lane = tid & 31, wid = tid >> 5;
    int wm = wid & 7, wn = wid >> 3;
    int nkt = 2 * qt + 2;

    if (tid < 128) Ls[tid] = 0.f;

    // Q tile (hi,lo), 128 rows
    {
        const __nv_bfloat16* qh = Qhi + ((size_t)(b * Tseq + q0)) * Dm + h * HD;
        const __nv_bfloat16* ql = Qlo + ((size_t)(b * Tseq + q0)) * Dm + h * HD;
#pragma unroll
        for (int i = 0; i < 4; i++) {
            int j = tid + i * 512;
            int row = j >> 4, c = j & 15;
            uint32_t so = row * KSTR + c * 16;
            size_t go = (size_t)row * Dm + c * 8;
            cpa16(sb + AQ_OFF + so, qh + go);
            cpa16(sb + AQ_OFF + QTILE + so, ql + go);
        }
        asm volatile("cp.async.commit_group;" ::: "memory");
    }
    {
        size_t base = (size_t)(b * Tseq) * HD;
        attn_load_stage(sb + AST_OFF, Khi + base, Klo + base, Vhi + base, Vlo + base, tid);
        size_t b1 = base + 64 * HD;
        attn_load_stage(sb + AST_OFF + ASTAGE, Khi + b1, Klo + b1, Vhi + b1, Vlo + b1, tid);
    }

    float acc[16][4];
#pragma unroll
    for (int f = 0; f < 16; f++)
#pragma unroll
        for (int j = 0; j < 4; j++) acc[f][j] = 0.f;

    const float cap2 = 2.0f * 0.0029462782549439483f;   // 2/(sqrt(128)*30)
    const float E30 = 1.0686474581524463e13f;           // exp(30)

    uint32_t aQoff = AQ_OFF + (wm * 16 + (lane & 15)) * KSTR + (lane >> 4) * 16;
    uint32_t bKrow = wn * 32 + (lane & 7) + ((lane >> 4) & 1) * 8;
    uint32_t bKoff = bKrow * KSTR + ((lane >> 3) & 1) * 16;

    for (int kt = 0; kt < nkt; kt++) {
        if (kt + 1 < nkt)
            asm volatile("cp.async.wait_group 1;" ::: "memory");
        else
            asm volatile("cp.async.wait_group 0;" ::: "memory");
        __syncthreads();

        // last tile (k0 = q0+64): rows 0..63 (warps wm<4) fully masked -> skip
        bool skipw = (kt == nkt - 1) && (wm < 4);
        if (!skipw) {
            uint32_t stK = sb + AST_OFF + (kt & 1) * ASTAGE;
            uint32_t stV = stK + 2 * KTILE;

            // ---- S = Q K^T (warp tile 16 x 32), 3-term split ----
            float sfrag[4][4];
#pragma unroll
            for (int f = 0; f < 4; f++)
#pragma unroll
                for (int e = 0; e < 4; e++) sfrag[f][e] = 0.f;

#pragma unroll
            for (int kb = 0; kb < 8; kb++) {
                uint32_t ah[4], al[4];
                ldsm4(ah, sb + aQoff + kb * 32);
                ldsm4(al, sb + aQoff + QTILE + kb * 32);
#pragma unroll
                for (int nb = 0; nb < 2; nb++) {
                    uint32_t bhh[4], bll[4];
                    uint32_t baddr = stK + bKoff + nb * 16 * KSTR + kb * 32;
                    ldsm4(bhh, baddr);
                    ldsm4(bll, baddr + KTILE);
                    mma16816(sfrag[nb * 2],     ah, &bhh[0]);
                    mma16816(sfrag[nb * 2],     ah, &bll[0]);
                    mma16816(sfrag[nb * 2],     al, &bhh[0]);
                    mma16816(sfrag[nb * 2 + 1], ah, &bhh[2]);
                    mma16816(sfrag[nb * 2 + 1], ah, &bll[2]);
                    mma16816(sfrag[nb * 2 + 1], al, &bhh[2]);
                }
            }

            // ---- softcap + causal mask + exp (in place), rowsum ----
            // p = exp(30*tanh(s*scale/30)) = E30 * exp(-60/(exp(2*s*scale/30)+1))
            bool diag = (kt >= nkt - 2);
            int ko = kt * 64 - q0;               // 0 or 64 on diag tiles
            int rloc = wm * 16 + (lane >> 2);
            float rs0 = 0.f, rs1 = 0.f;
#pragma unroll
            for (int nf = 0; nf < 4; nf++) {
                int colb = wn * 32 + nf * 8 + 2 * (lane & 3);
#pragma unroll
                for (int e = 0; e < 4; e++) {
                    int row = rloc + ((e >> 1) << 3);
                    int col = colb + (e & 1);
                    float ex = __expf(sfrag[nf][e] * cap2);
                    float pv = E30 * __expf(-__fdividef(60.f, ex + 1.f));
                    if (diag && col + ko > row) pv = 0.f;
                    sfrag[nf][e] = pv;
                    if (e < 2) rs0 += pv; else rs1 += pv;
                }
            }
            rs0 += __shfl_xor_sync(0xffffffffu, rs0, 1);
            rs0 += __shfl_xor_sync(0xffffffffu, rs0, 2);
            rs1 += __shfl_xor_sync(0xffffffffu, rs1, 1);
            rs1 += __shfl_xor_sync(0xffffffffu, rs1, 2);
            if ((lane & 3) == 0) {
                atomicAdd(&Ls[rloc], rs0);
                atomicAdd(&Ls[rloc + 8], rs1);
            }

            // ---- P -> A frags (split) ----
            uint32_t aPh[2][4], aPl[2][4];
#pragma unroll
            for (int kb2 = 0; kb2 < 2; kb2++) {
                int j = kb2 * 2;
                split_pack2(sfrag[j][0],     sfrag[j][1],     aPh[kb2][0], aPl[kb2][0]);
                split_pack2(sfrag[j][2],     sfrag[j][3],     aPh[kb2][1], aPl[kb2][1]);
                split_pack2(sfrag[j + 1][0], sfrag[j + 1][1], aPh[kb2][2], aPl[kb2][2]);
                split_pack2(sfrag[j + 1][2], sfrag[j + 1][3], aPh[kb2][3], aPl[kb2][3]);
            }

            // ---- acc += P @ V (k-slice = warp's 32 cols) ----
#pragma unroll
            for (int kb2 = 0; kb2 < 2; kb2++) {
                int t0 = wn * 32 + kb2 * 16;
                uint32_t vAddr0 = stV + (t0 + (lane & 15)) * KSTR + (lane >> 4) * 16;
#pragma unroll
                for (int nb = 0; nb < 8; nb++) {
                    uint32_t vh[4], vl[4];
                    uint32_t va = vAddr0 + nb * 32;
                    ldsm4t(vh, va);
                    ldsm4t(vl, va + KTILE);
                    mma16816(acc[nb * 2],     aPh[kb2], &vh[0]);
                    mma16816(acc[nb * 2],     aPh[kb2], &vl[0]);
                    mma16816(acc[nb * 2],     aPl[kb2], &vh[0]);
                    mma16816(acc[nb * 2 + 1], aPh[kb2], &vh[2]);
                    mma16816(acc[nb * 2 + 1], aPh[kb2], &vl[2]);
                    mma16816(acc[nb * 2 + 1], aPl[kb2], &vh[2]);
                }
            }
        }

        __syncthreads();
        if (kt + 2 < nkt) {
            size_t bn = (size_t)(b * Tseq + (kt + 2) * 64) * HD;
            attn_load_stage(sb + AST_OFF + (kt & 1) * ASTAGE,
                            Khi + bn, Klo + bn, Vhi + bn, Vlo + bn, tid);
        }
    }

    __syncthreads();

    // ---- cross-warp (wn) reduction via smem, normalize, write AO ----
    float* red = (float*)(sm + AST_OFF);     // 128x128 fp32 = 64KB, fits stages
    int rloc = wm * 16 + (lane >> 2);
    if (wn == 1) {
#pragma unroll
        for (int nn = 0; nn < 16; nn++) {
            int col = nn * 8 + 2 * (lane & 3);
            red[rloc * 128 + col] = acc[nn][0];
            red[rloc * 128 + col + 1] = acc[nn][1];
            red[(rloc + 8) * 128 + col] = acc[nn][2];
            red[(rloc + 8) * 128 + col + 1] = acc[nn][3];
        }
    }
    __syncthreads();
    if (wn == 0) {
        float inv0 = __fdividef(1.f, Ls[rloc]);
        float inv1 = __fdividef(1.f, Ls[rloc + 8]);
        size_t r0g = ((size_t)(b * Tseq + q0 + rloc)) * Dm + h * HD;
        size_t r1g = r0g + 8 * (size_t)Dm;
#pragma unroll
        for (int nn = 0; nn < 16; nn++) {
            int col = nn * 8 + 2 * (lane & 3);
            float o0 = (acc[nn][0] + red[rloc * 128 + col]) * inv0;
            float o1 = (acc[nn][1] + red[rloc * 128 + col + 1]) * inv0;
            float o2 = (acc[nn][2] + red[(rloc + 8) * 128 + col]) * inv1;
            float o3 = (acc[nn][3] + red[(rloc + 8) * 128 + col + 1]) * inv1;
            uint32_t h01, l01, h23, l23;
            split_pack2(o0, o1, h01, l01);
            split_pack2(o2, o3, h23, l23);
            *(uint32_t*)(AOhi + r0g + col) = h01;
            *(uint32_t*)(AOlo + r0g + col) = l01;
            *(uint32_t*)(AOhi + r1g + col) = h23;
            *(uint32_t*)(AOlo + r1g + col) = l23;
        }
    }
}

// ---------------------------------------------------------------------------
extern "C" void kernel_launch(void* const* d_in, const int* in_sizes, int n_in,
                              void* d_out, int out_size)
{
    const float* x    = (const float*)d_in[0];
    const float* Wq   = (const float*)d_in[1];
    const float* Wk   = (const float*)d_in[2];
    const float* Wv   = (const float*)d_in[3];
    const float* Wo   = (const float*)d_in[4];
    const float* gain = (const float*)d_in[5];
    const float* cosb = (const float*)d_in[6];
    const float* sinb = (const float*)d_in[7];
    float* out = (float*)d_out;

    __nv_bfloat16 *xhi, *xlo, *Whi, *Wlo, *Qhi, *Qlo, *Khi, *Klo, *Vhi, *Vlo, *AOhi, *AOlo;
    float *QKV;
    cudaGetSymbolAddress((void**)&xhi, g_xhi);
    cudaGetSymbolAddress((void**)&xlo, g_xlo);
    cudaGetSymbolAddress((void**)&Whi, g_Whi);
    cudaGetSymbolAddress((void**)&Wlo, g_Wlo);
    cudaGetSymbolAddress((void**)&QKV, g_QKV);
    cudaGetSymbolAddress((void**)&Qhi, g_Qhi);
    cudaGetSymbolAddress((void**)&Qlo, g_Qlo);
    cudaGetSymbolAddress((void**)&Khi, g_Khi);
    cudaGetSymbolAddress((void**)&Klo, g_Klo);
    cudaGetSymbolAddress((void**)&Vhi, g_Vhi);
    cudaGetSymbolAddress((void**)&Vlo, g_Vlo);
    cudaGetSymbolAddress((void**)&AOhi, g_AOhi);
    cudaGetSymbolAddress((void**)&AOlo, g_AOlo);

    const int nx = MTOT * Dm;

    split_kernel<<<nx / 4 / 256, 256>>>(x, xhi, xlo, nx);
    split_w4_kernel<<<(NWROWS * Dm) / 4 / 256, 256>>>(Wq, Wk, Wv, Wo, Whi, Wlo);

    cudaFuncSetAttribute(gemm_hmma_kernel, cudaFuncAttributeMaxDynamicSharedMemorySize, GEMM_SMEM);

    // fused QKV projection
    gemm_hmma_kernel<<<dim3(NQKV / 128, MTOT / 128), 256, GEMM_SMEM>>>(
        xhi, xlo, Whi, Wlo, QKV, NQKV);

    // RoPE + split to bf16
    rope_q_split<<<(Bx * Tseq * NH * 64) / 256, 256>>>(QKV, cosb, sinb, gain, Qhi, Qlo);
    rope_k_split<<<(Bx * Tseq * 64) / 256, 256>>>(QKV, cosb, sinb, Khi, Klo);
    v_split<<<(Bx * Tseq * HD) / 256, 256>>>(QKV, Vhi, Vlo);

    // Attention (HMMA, 128-row q-tiles, 512 threads)
    cudaFuncSetAttribute(attn_hmma_kernel, cudaFuncAttributeMaxDynamicSharedMemorySize, ATTN_SMEM);
    attn_hmma_kernel<<<dim3(Tseq / 128, NH, Bx), 512, ATTN_SMEM>>>(
        Qhi, Qlo, Khi, Klo, Vhi, Vlo, AOhi, AOlo);

    // Output projection
    gemm_hmma_kernel<<<dim3(Dm / 128, MTOT / 128), 256, GEMM_SMEM>>>(
        AOhi, AOlo, Whi + (size_t)1280 * Dm, Wlo + (size_t)1280 * Dm, out, Dm);
}